// round 3
// baseline (speedup 1.0000x reference)
#include <cuda_runtime.h>
#include <cuda_bf16.h>
#include <cstdint>
#include <math.h>

typedef unsigned long long ull;

// ---------------- device scratch (static; no runtime allocation) ----------------
__device__ float g_A1[64*64];
__device__ float g_A2[64*64];
__device__ float g_henc[4096UL*256*32];     // GNN out, (seq n=b*64+c, t, g)
__device__ float g_h0[4096UL*256*128];      // BiGRU L0 out, (n, t, dir*64+h)
__device__ float g_last[4096*128];          // L1 last-step concat (n, 128)
__device__ float g_dxg[64*256];             // decoder LSTM L1 const gates (b, 256)
__device__ float g_h1d[64UL*256*64];        // decoder LSTM L1 hidden seq

// ---------------- helpers ----------------
__device__ __forceinline__ void fma2(ull &acc, ull a, ull b){
    asm("fma.rn.f32x2 %0, %1, %2, %0;" : "+l"(acc) : "l"(a), "l"(b));
}
__device__ __forceinline__ float hsum2(ull a){
    float lo, hi; asm("mov.b64 {%0,%1}, %2;" : "=f"(lo), "=f"(hi) : "l"(a));
    return lo + hi;
}
__device__ __forceinline__ float sigf(float x){ return 1.f/(1.f + expf(-x)); }

// ---------------- K1: row softmax of adj1, adj2 ----------------
__global__ void k_softmax(const float* __restrict__ adj1, const float* __restrict__ adj2){
    int i = threadIdx.x;  // 64 threads, one row each
    for (int w = 0; w < 2; w++){
        const float* a = w ? adj2 : adj1;
        float* o = w ? g_A2 : g_A1;
        float mx = -1e30f;
        for (int j = 0; j < 64; j++) mx = fmaxf(mx, a[i*64+j]);
        float s = 0.f;
        for (int j = 0; j < 64; j++) s += expf(a[i*64+j] - mx);
        float inv = 1.f / s;
        for (int j = 0; j < 64; j++) o[i*64+j] = expf(a[i*64+j] - mx) * inv;
    }
}

// ---------------- K2: GNN encoder, one block per (b,t) ----------------
__global__ __launch_bounds__(256) void k_gnn(
    const float* __restrict__ x,
    const float* __restrict__ W1, const float* __restrict__ b1,
    const float* __restrict__ W2, const float* __restrict__ b2,
    const float* __restrict__ lng, const float* __restrict__ lnb)
{
    int bt = blockIdx.x;
    int b = bt >> 8, t = bt & 255;
    int tid = threadIdx.x;

    __shared__ float sA2[64*65];                  // padded, conflict-free
    __shared__ float sW2t[1024];                  // transposed W2: [k][g']
    __shared__ __align__(16) float sx[64];
    __shared__ float s1[64];
    __shared__ __align__(16) float sh1[2048];     // [j][g]
    __shared__ __align__(16) float sagg[2048];    // [i][g]
    __shared__ float sh2[64*33];                  // padded
    __shared__ float sW1[32], sb1[32], sb2[32], slg[32], slb[32];
    __shared__ float smean[64], srstd[64];

    for (int i = tid; i < 4096; i += 256) sA2[(i>>6)*65 + (i&63)] = g_A2[i];
    for (int i = tid; i < 1024; i += 256){ int gp = i>>5, k = i&31; sW2t[k*32+gp] = W2[i]; }
    if (tid < 64) sx[tid] = x[(size_t)bt*64 + tid];
    if (tid < 32){ sW1[tid]=W1[tid]; sb1[tid]=b1[tid]; sb2[tid]=b2[tid]; slg[tid]=lng[tid]; slb[tid]=lnb[tid]; }
    __syncthreads();

    // s1 = A1 @ x
    if (tid < 64){
        float s = 0.f; const float* a = g_A1 + tid*64;
        #pragma unroll 8
        for (int j = 0; j < 64; j++) s += a[j]*sx[j];
        s1[tid] = s;
    }
    __syncthreads();

    // h1[j][g] = relu(W1[g]*s1[j] + b1[g])
    for (int i = tid; i < 2048; i += 256){ int j = i>>5, g = i&31; sh1[i] = fmaxf(sW1[g]*s1[j] + sb1[g], 0.f); }
    __syncthreads();

    // agg[i][g] = sum_j A2[i][j] * h1[j][g]
    {
        int i = tid >> 2, g0 = (tid & 3) * 8;
        float4 a0 = {0,0,0,0}, a1 = {0,0,0,0};
        #pragma unroll 4
        for (int j = 0; j < 64; j++){
            float a = sA2[i*65 + j];
            float4 h0 = *(const float4*)(sh1 + j*32 + g0);
            float4 h1 = *(const float4*)(sh1 + j*32 + g0 + 4);
            a0.x += a*h0.x; a0.y += a*h0.y; a0.z += a*h0.z; a0.w += a*h0.w;
            a1.x += a*h1.x; a1.y += a*h1.y; a1.z += a*h1.z; a1.w += a*h1.w;
        }
        *(float4*)(sagg + i*32 + g0)     = a0;
        *(float4*)(sagg + i*32 + g0 + 4) = a1;
    }
    __syncthreads();

    // h2[i][g'] = relu(agg[i] . W2[g'] + b2[g'])
    #pragma unroll
    for (int q = 0; q < 8; q++){
        int idx = tid + (q << 8);
        int i = idx >> 5, gp = idx & 31;
        float acc = sb2[gp];
        #pragma unroll 8
        for (int k = 0; k < 32; k++) acc += sagg[i*32 + k] * sW2t[k*32 + gp];
        sh2[i*33 + gp] = fmaxf(acc, 0.f);
    }
    __syncthreads();

    // LayerNorm over g
    if (tid < 64){
        float m = 0.f;
        for (int g = 0; g < 32; g++) m += sh2[tid*33 + g];
        m *= (1.f/32.f);
        float v = 0.f;
        for (int g = 0; g < 32; g++){ float d = sh2[tid*33 + g] - m; v += d*d; }
        v *= (1.f/32.f);
        smean[tid] = m; srstd[tid] = rsqrtf(v + 1e-5f);
    }
    __syncthreads();

    for (int idx = tid; idx < 2048; idx += 256){
        int i = idx >> 5, g = idx & 31;
        float val = (sh2[i*33 + g] - smean[i]) * srstd[i] * slg[g] + slb[g];
        g_henc[(((size_t)b*64 + i)*256 + t)*32 + g] = val;
    }
}

// ---------------- K3: BiGRU layer 0, one block per (n, dir) ----------------
__global__ __launch_bounds__(192,2) void k_gru0(
    const float* __restrict__ Wih, const float* __restrict__ Whh,
    const float* __restrict__ bih, const float* __restrict__ bhh)
{
    int n = blockIdx.x, dir = blockIdx.y;
    int g = threadIdx.x;   // gate row 0..191
    __shared__ __align__(16) float sx[32];
    __shared__ __align__(16) float sh[64];
    __shared__ float sgi[192], sgh[192];

    ull wi[16], wh[32];
    {
        const ull* p = (const ull*)(Wih + ((size_t)dir*192 + g)*32);
        #pragma unroll
        for (int k = 0; k < 16; k++) wi[k] = p[k];
        const ull* q = (const ull*)(Whh + ((size_t)dir*192 + g)*64);
        #pragma unroll
        for (int k = 0; k < 32; k++) wh[k] = q[k];
    }
    float bi = bih[dir*192 + g], bh = bhh[dir*192 + g];

    const float* xbase = g_henc + (size_t)n*256*32;
    float* obase = g_h0 + (size_t)n*256*128 + dir*64;

    if (g < 64) sh[g] = 0.f;
    int t0 = dir ? 255 : 0;
    float xreg = (g < 32) ? xbase[t0*32 + g] : 0.f;

    for (int s = 0; s < 256; s++){
        int t = dir ? 255 - s : s;
        if (g < 32) sx[g] = xreg;
        __syncthreads();
        if (g < 32 && s < 255){
            int tn = dir ? 254 - s : s + 1;
            xreg = xbase[tn*32 + g];
        }
        const ulonglong2* x4 = (const ulonglong2*)sx;
        const ulonglong2* h4 = (const ulonglong2*)sh;
        ull a0 = 0, a1 = 0;
        #pragma unroll
        for (int k = 0; k < 8; k++){ ulonglong2 v = x4[k]; fma2(a0, wi[2*k], v.x); fma2(a1, wi[2*k+1], v.y); }
        ull b0 = 0, b1 = 0;
        #pragma unroll
        for (int k = 0; k < 16; k++){ ulonglong2 v = h4[k]; fma2(b0, wh[2*k], v.x); fma2(b1, wh[2*k+1], v.y); }
        sgi[g] = hsum2(a0) + hsum2(a1) + bi;
        sgh[g] = hsum2(b0) + hsum2(b1) + bh;
        __syncthreads();
        if (g < 64){
            float r  = sigf(sgi[g] + sgh[g]);
            float z  = sigf(sgi[64+g] + sgh[64+g]);
            float nn = tanhf(sgi[128+g] + r*sgh[128+g]);
            float h  = (1.f - z)*nn + z*sh[g];
            sh[g] = h;
            obase[t*128 + g] = h;
        }
    }
}

// ---------------- K4a: GRU layer 1 forward (only last h needed) ----------------
__global__ __launch_bounds__(384,1) void k_gru1f(
    const float* __restrict__ Wih, const float* __restrict__ Whh,
    const float* __restrict__ bih, const float* __restrict__ bhh)
{
    int n = blockIdx.x;
    int tid = threadIdx.x;
    bool isA = tid < 192;             // A: input proj (128); B: hidden proj (64)
    int g = isA ? tid : tid - 192;
    __shared__ __align__(16) float sx[128];
    __shared__ __align__(16) float sh[64];
    __shared__ float sgi[192], sgh[192];

    ull w[64];
    if (isA){
        const ull* p = (const ull*)(Wih + (size_t)g*128);       // dir 0
        #pragma unroll
        for (int k = 0; k < 64; k++) w[k] = p[k];
    } else {
        const ull* p = (const ull*)(Whh + (size_t)g*64);        // dir 0
        #pragma unroll
        for (int k = 0; k < 32; k++) w[k] = p[k];
    }
    float bias = isA ? bih[g] : bhh[g];

    const float* xbase = g_h0 + (size_t)n*256*128;
    if (tid < 64) sh[tid] = 0.f;
    float xreg = (tid < 128) ? xbase[tid] : 0.f;

    for (int t = 0; t < 256; t++){
        if (tid < 128) sx[tid] = xreg;
        __syncthreads();
        if (tid < 128 && t < 255) xreg = xbase[(size_t)(t+1)*128 + tid];
        ull a0 = 0, a1 = 0;
        if (isA){
            const ulonglong2* v4 = (const ulonglong2*)sx;
            #pragma unroll
            for (int k = 0; k < 32; k++){ ulonglong2 v = v4[k]; fma2(a0, w[2*k], v.x); fma2(a1, w[2*k+1], v.y); }
            sgi[g] = hsum2(a0) + hsum2(a1) + bias;
        } else {
            const ulonglong2* v4 = (const ulonglong2*)sh;
            #pragma unroll
            for (int k = 0; k < 16; k++){ ulonglong2 v = v4[k]; fma2(a0, w[2*k], v.x); fma2(a1, w[2*k+1], v.y); }
            sgh[g] = hsum2(a0) + hsum2(a1) + bias;
        }
        __syncthreads();
        if (tid < 64){
            float r  = sigf(sgi[tid] + sgh[tid]);
            float z  = sigf(sgi[64+tid] + sgh[64+tid]);
            float nn = tanhf(sgi[128+tid] + r*sgh[128+tid]);
            float h  = (1.f - z)*nn + z*sh[tid];
            sh[tid] = h;
            if (t == 255) g_last[n*128 + tid] = h;
        }
    }
}

// ---------------- K4b: GRU layer 1 backward = single step from h0=0 ----------------
__global__ __launch_bounds__(192,2) void k_gru1b(
    const float* __restrict__ Wih, const float* __restrict__ Whh,
    const float* __restrict__ bih, const float* __restrict__ bhh)
{
    int tid = threadIdx.x;   // gate row, dir 1
    __shared__ __align__(16) float sx[128];
    __shared__ float sgi[192];
    ull w[64];
    const ull* p = (const ull*)(Wih + 192UL*128 + (size_t)tid*128);
    #pragma unroll
    for (int k = 0; k < 64; k++) w[k] = p[k];
    float bias = bih[192 + tid];

    for (int it = 0; it < 64; it++){
        int n = blockIdx.x*64 + it;
        if (tid < 128) sx[tid] = g_h0[((size_t)n*256 + 255)*128 + tid];
        __syncthreads();
        ull a0 = 0, a1 = 0;
        const ulonglong2* v4 = (const ulonglong2*)sx;
        #pragma unroll
        for (int k = 0; k < 32; k++){ ulonglong2 v = v4[k]; fma2(a0, w[2*k], v.x); fma2(a1, w[2*k+1], v.y); }
        sgi[tid] = hsum2(a0) + hsum2(a1) + bias;
        __syncthreads();
        if (tid < 64){
            float r  = sigf(sgi[tid]      + bhh[192 + tid]);
            float z  = sigf(sgi[64 + tid] + bhh[192 + 64 + tid]);
            float nn = tanhf(sgi[128+tid] + r * bhh[192 + 128 + tid]);
            g_last[n*128 + 64 + tid] = (1.f - z)*nn;
        }
    }
}

// ---------------- K5: pooling + VAE head + decoder fc + LSTM-L1 const gates ----------------
__global__ __launch_bounds__(128) void k_head(
    const float* __restrict__ pool_W, const float* __restrict__ pool_b,
    const float* __restrict__ mu_W, const float* __restrict__ mu_b,
    const float* __restrict__ logv_W, const float* __restrict__ logv_b,
    const float* __restrict__ dec_W, const float* __restrict__ dec_b,
    const float* __restrict__ lstm_Wih, const float* __restrict__ lstm_bih,
    const float* __restrict__ lstm_bhh,
    float* __restrict__ out)
{
    int b = blockIdx.x, tid = threadIdx.x;
    __shared__ float slast[128], shp[32], smu[32], sdh[64];
    float s = 0.f;
    for (int c = 0; c < 64; c++) s += g_last[(b*64 + c)*128 + tid];
    slast[tid] = s * (1.f/64.f);
    __syncthreads();
    if (tid < 32){
        float acc = pool_b[tid];
        for (int k = 0; k < 128; k++) acc += pool_W[tid*128 + k] * slast[k];
        shp[tid] = fmaxf(acc, 0.f);
    }
    __syncthreads();
    if (tid < 32){
        float acc = mu_b[tid];
        for (int k = 0; k < 32; k++) acc += mu_W[tid*32 + k] * shp[k];
        smu[tid] = acc;
        out[64UL*256*64 + b*32 + tid] = acc;
    } else if (tid < 64){
        int j = tid - 32;
        float acc = logv_b[j];
        for (int k = 0; k < 32; k++) acc += logv_W[j*32 + k] * shp[k];
        out[64UL*256*64 + 2048 + b*32 + j] = acc;
    }
    __syncthreads();
    if (tid < 64){
        float acc = dec_b[tid];
        for (int k = 0; k < 32; k++) acc += dec_W[tid*32 + k] * smu[k];
        sdh[tid] = fmaxf(acc, 0.f);
    }
    __syncthreads();
    for (int gate = tid; gate < 256; gate += 128){
        float acc = lstm_bih[gate] + lstm_bhh[gate];   // layer 0
        for (int k = 0; k < 64; k++) acc += lstm_Wih[gate*64 + k] * sdh[k];
        g_dxg[b*256 + gate] = acc;
    }
}

// ---------------- K6: decoder LSTM layer 1 (constant input gates) ----------------
__global__ __launch_bounds__(256,1) void k_lstm1(const float* __restrict__ Whh)
{
    int b = blockIdx.x, tid = threadIdx.x;
    __shared__ __align__(16) float sh[64];
    __shared__ float sg[256];
    ull w[32];
    const ull* p = (const ull*)(Whh + (size_t)tid*64);   // layer 0
    #pragma unroll
    for (int k = 0; k < 32; k++) w[k] = p[k];
    float dxg = g_dxg[b*256 + tid];
    if (tid < 64) sh[tid] = 0.f;
    float c = 0.f;
    for (int t = 0; t < 256; t++){
        __syncthreads();
        ull a0 = 0, a1 = 0;
        const ulonglong2* v4 = (const ulonglong2*)sh;
        #pragma unroll
        for (int k = 0; k < 16; k++){ ulonglong2 v = v4[k]; fma2(a0, w[2*k], v.x); fma2(a1, w[2*k+1], v.y); }
        sg[tid] = hsum2(a0) + hsum2(a1) + dxg;
        __syncthreads();
        if (tid < 64){
            float i_ = sigf(sg[tid]), f_ = sigf(sg[64+tid]);
            float gg = tanhf(sg[128+tid]), o_ = sigf(sg[192+tid]);
            c = f_*c + i_*gg;
            float h = o_*tanhf(c);
            sh[tid] = h;
            g_h1d[((size_t)b*256 + t)*64 + tid] = h;
        }
    }
}

// ---------------- K7: decoder LSTM layer 2 + fused output projection ----------------
__global__ __launch_bounds__(256,1) void k_lstm2(
    const float* __restrict__ Wih, const float* __restrict__ Whh,
    const float* __restrict__ bih, const float* __restrict__ bhh,
    const float* __restrict__ out_W, const float* __restrict__ out_b,
    float* __restrict__ out)
{
    int b = blockIdx.x, tid = threadIdx.x;
    __shared__ __align__(16) float sx[64];
    __shared__ __align__(16) float sh[64];
    __shared__ float sg[256];
    __shared__ float soW[64*64];     // transposed: soW[k*64+c] = out_W[c*64+k]
    for (int i = tid; i < 4096; i += 256){ int c = i >> 6, k = i & 63; soW[k*64 + c] = out_W[i]; }
    ull wi[32], wh[32];
    const ull* p = (const ull*)(Wih + 256UL*64 + (size_t)tid*64);
    const ull* q = (const ull*)(Whh + 256UL*64 + (size_t)tid*64);
    #pragma unroll
    for (int k = 0; k < 32; k++){ wi[k] = p[k]; wh[k] = q[k]; }
    float bias = bih[256 + tid] + bhh[256 + tid];
    if (tid < 64) sh[tid] = 0.f;
    float c = 0.f;
    float ob = (tid >= 64 && tid < 128) ? out_b[tid - 64] : 0.f;
    const float* xb = g_h1d + (size_t)b*256*64;
    for (int t = 0; t < 256; t++){
        if (tid < 64) sx[tid] = xb[t*64 + tid];
        __syncthreads();
        ull a0 = 0, a1 = 0;
        const ulonglong2* x4 = (const ulonglong2*)sx;
        const ulonglong2* h4 = (const ulonglong2*)sh;
        #pragma unroll
        for (int k = 0; k < 16; k++){ ulonglong2 v = x4[k]; fma2(a0, wi[2*k], v.x); fma2(a1, wi[2*k+1], v.y); }
        #pragma unroll
        for (int k = 0; k < 16; k++){ ulonglong2 v = h4[k]; fma2(a0, wh[2*k], v.x); fma2(a1, wh[2*k+1], v.y); }
        sg[tid] = hsum2(a0) + hsum2(a1) + bias;
        __syncthreads();
        if (tid < 64){
            float i_ = sigf(sg[tid]), f_ = sigf(sg[64+tid]);
            float gg = tanhf(sg[128+tid]), o_ = sigf(sg[192+tid]);
            c = f_*c + i_*gg;
            sh[tid] = o_*tanhf(c);
        }
        __syncthreads();
        if (tid >= 64 && tid < 128){
            int cc = tid - 64;
            float acc = ob;
            #pragma unroll 8
            for (int k = 0; k < 64; k++) acc += soW[k*64 + cc] * sh[k];
            out[((size_t)b*256 + t)*64 + cc] = acc;
        }
    }
}

extern "C" void kernel_launch(void* const* d_in, const int* in_sizes, int n_in,
                              void* d_out, int out_size)
{
    const float* x      = (const float*)d_in[0];
    const float* adj1   = (const float*)d_in[1];
    const float* W1     = (const float*)d_in[2];
    const float* b1     = (const float*)d_in[3];
    const float* adj2   = (const float*)d_in[4];
    const float* W2     = (const float*)d_in[5];
    const float* b2     = (const float*)d_in[6];
    const float* ln_g   = (const float*)d_in[7];
    const float* ln_b   = (const float*)d_in[8];
    const float* g0Wih  = (const float*)d_in[9];
    const float* g0Whh  = (const float*)d_in[10];
    const float* g0bih  = (const float*)d_in[11];
    const float* g0bhh  = (const float*)d_in[12];
    const float* g1Wih  = (const float*)d_in[13];
    const float* g1Whh  = (const float*)d_in[14];
    const float* g1bih  = (const float*)d_in[15];
    const float* g1bhh  = (const float*)d_in[16];
    const float* pool_W = (const float*)d_in[17];
    const float* pool_b = (const float*)d_in[18];
    const float* mu_W   = (const float*)d_in[19];
    const float* mu_b   = (const float*)d_in[20];
    const float* logv_W = (const float*)d_in[21];
    const float* logv_b = (const float*)d_in[22];
    const float* dec_W  = (const float*)d_in[23];
    const float* dec_b  = (const float*)d_in[24];
    const float* lWih   = (const float*)d_in[25];
    const float* lWhh   = (const float*)d_in[26];
    const float* lbih   = (const float*)d_in[27];
    const float* lbhh   = (const float*)d_in[28];
    const float* out_W  = (const float*)d_in[29];
    const float* out_b  = (const float*)d_in[30];
    float* out = (float*)d_out;

    k_softmax<<<1, 64>>>(adj1, adj2);
    k_gnn<<<16384, 256>>>(x, W1, b1, W2, b2, ln_g, ln_b);
    k_gru0<<<dim3(4096, 2), 192>>>(g0Wih, g0Whh, g0bih, g0bhh);
    k_gru1f<<<4096, 384>>>(g1Wih, g1Whh, g1bih, g1bhh);
    k_gru1b<<<64, 192>>>(g1Wih, g1Whh, g1bih, g1bhh);
    k_head<<<64, 128>>>(pool_W, pool_b, mu_W, mu_b, logv_W, logv_b,
                        dec_W, dec_b, lWih, lbih, lbhh, out);
    k_lstm1<<<64, 256>>>(lWhh);
    k_lstm2<<<64, 256>>>(lWih, lWhh, lbih, lbhh, out_W, out_b, out);
}

// round 5
// speedup vs baseline: 1.1182x; 1.1182x over previous
#include <cuda_runtime.h>
#include <cuda_bf16.h>
#include <cstdint>
#include <math.h>

typedef unsigned long long ull;

__device__ float g_A1[64*64];
__device__ float g_A2[64*64];
__device__ float g_henc[4096UL*256*32];
__device__ float g_h0[4096UL*256*128];
__device__ float g_last[4096*128];
__device__ float g_dxg[64*256];
__device__ float g_h1d[64UL*256*64];

__device__ __forceinline__ void fma2(ull &acc, ull a, ull b){
    asm("fma.rn.f32x2 %0, %1, %2, %0;" : "+l"(acc) : "l"(a), "l"(b));
}
__device__ __forceinline__ float hsum2(ull a){
    float lo, hi; asm("mov.b64 {%0,%1}, %2;" : "=f"(lo), "=f"(hi) : "l"(a));
    return lo + hi;
}
__device__ __forceinline__ float sigf(float x){ return 1.f/(1.f + expf(-x)); }

__global__ void k_softmax(const float* __restrict__ adj1, const float* __restrict__ adj2){
    int i = threadIdx.x;
    for (int w = 0; w < 2; w++){
        const float* a = w ? adj2 : adj1;
        float* o = w ? g_A2 : g_A1;
        float mx = -1e30f;
        for (int j = 0; j < 64; j++) mx = fmaxf(mx, a[i*64+j]);
        float s = 0.f;
        for (int j = 0; j < 64; j++) s += expf(a[i*64+j] - mx);
        float inv = 1.f / s;
        for (int j = 0; j < 64; j++) o[i*64+j] = expf(a[i*64+j] - mx) * inv;
    }
}

__global__ __launch_bounds__(256) void k_gnn(
    const float* __restrict__ x,
    const float* __restrict__ W1, const float* __restrict__ b1,
    const float* __restrict__ W2, const float* __restrict__ b2,
    const float* __restrict__ lng, const float* __restrict__ lnb)
{
    int bt = blockIdx.x;
    int b = bt >> 8, t = bt & 255;
    int tid = threadIdx.x;

    __shared__ float sA2[64*65];
    __shared__ float sW2t[1024];
    __shared__ __align__(16) float sx[64];
    __shared__ float s1[64];
    __shared__ __align__(16) float sh1[2048];
    __shared__ __align__(16) float sagg[2048];
    __shared__ float sh2[64*33];
    __shared__ float sW1[32], sb1[32], sb2[32], slg[32], slb[32];
    __shared__ float smean[64], srstd[64];

    for (int i = tid; i < 4096; i += 256) sA2[(i>>6)*65 + (i&63)] = g_A2[i];
    for (int i = tid; i < 1024; i += 256){ int gp = i>>5, k = i&31; sW2t[k*32+gp] = W2[i]; }
    if (tid < 64) sx[tid] = x[(size_t)bt*64 + tid];
    if (tid < 32){ sW1[tid]=W1[tid]; sb1[tid]=b1[tid]; sb2[tid]=b2[tid]; slg[tid]=lng[tid]; slb[tid]=lnb[tid]; }
    __syncthreads();

    if (tid < 64){
        float s = 0.f; const float* a = g_A1 + tid*64;
        #pragma unroll 8
        for (int j = 0; j < 64; j++) s += a[j]*sx[j];
        s1[tid] = s;
    }
    __syncthreads();

    for (int i = tid; i < 2048; i += 256){ int j = i>>5, g = i&31; sh1[i] = fmaxf(sW1[g]*s1[j] + sb1[g], 0.f); }
    __syncthreads();

    {
        int i = tid >> 2, g0 = (tid & 3) * 8;
        float4 a0 = {0,0,0,0}, a1 = {0,0,0,0};
        #pragma unroll 4
        for (int j = 0; j < 64; j++){
            float a = sA2[i*65 + j];
            float4 h0 = *(const float4*)(sh1 + j*32 + g0);
            float4 h1 = *(const float4*)(sh1 + j*32 + g0 + 4);
            a0.x += a*h0.x; a0.y += a*h0.y; a0.z += a*h0.z; a0.w += a*h0.w;
            a1.x += a*h1.x; a1.y += a*h1.y; a1.z += a*h1.z; a1.w += a*h1.w;
        }
        *(float4*)(sagg + i*32 + g0)     = a0;
        *(float4*)(sagg + i*32 + g0 + 4) = a1;
    }
    __syncthreads();

    #pragma unroll
    for (int q = 0; q < 8; q++){
        int idx = tid + (q << 8);
        int i = idx >> 5, gp = idx & 31;
        float acc = sb2[gp];
        #pragma unroll 8
        for (int k = 0; k < 32; k++) acc += sagg[i*32 + k] * sW2t[k*32 + gp];
        sh2[i*33 + gp] = fmaxf(acc, 0.f);
    }
    __syncthreads();

    if (tid < 64){
        float m = 0.f;
        for (int g = 0; g < 32; g++) m += sh2[tid*33 + g];
        m *= (1.f/32.f);
        float v = 0.f;
        for (int g = 0; g < 32; g++){ float d = sh2[tid*33 + g] - m; v += d*d; }
        v *= (1.f/32.f);
        smean[tid] = m; srstd[tid] = rsqrtf(v + 1e-5f);
    }
    __syncthreads();

    for (int idx = tid; idx < 2048; idx += 256){
        int i = idx >> 5, g = idx & 31;
        float val = (sh2[i*33 + g] - smean[i]) * srstd[i] * slg[g] + slb[g];
        g_henc[(((size_t)b*64 + i)*256 + t)*32 + g] = val;
    }
}

// ---- BiGRU layer 0: 4 sequences per CTA ----
__global__ __launch_bounds__(192,2) void k_gru0(
    const float* __restrict__ Wih, const float* __restrict__ Whh,
    const float* __restrict__ bih, const float* __restrict__ bhh)
{
    int n0 = blockIdx.x * 4, dir = blockIdx.y;
    int g = threadIdx.x;
    __shared__ __align__(16) float sx[4][32];
    __shared__ __align__(16) float sh[4][64];
    __shared__ float sgi[4][192], sgh[4][192];

    ull wi[16], wh[32];
    {
        const ull* p = (const ull*)(Wih + ((size_t)dir*192 + g)*32);
        #pragma unroll
        for (int k = 0; k < 16; k++) wi[k] = p[k];
        const ull* q = (const ull*)(Whh + ((size_t)dir*192 + g)*64);
        #pragma unroll
        for (int k = 0; k < 32; k++) wh[k] = q[k];
    }
    float bi = bih[dir*192+g], bh = bhh[dir*192+g];

    const float* xbase = g_henc + (size_t)n0*256*32;
    float* obase = g_h0 + (size_t)n0*256*128 + dir*64;

    if (g < 64){ sh[0][g]=0.f; sh[1][g]=0.f; sh[2][g]=0.f; sh[3][g]=0.f; }
    int ps = g >> 5, pg = g & 31;
    int t0 = dir ? 255 : 0;
    float xreg = (g < 128) ? xbase[((size_t)ps*256 + t0)*32 + pg] : 0.f;

    for (int s = 0; s < 256; s++){
        int t = dir ? 255 - s : s;
        if (g < 128) sx[ps][pg] = xreg;
        __syncthreads();
        if (g < 128 && s < 255){
            int tn = dir ? 254 - s : s + 1;
            xreg = xbase[((size_t)ps*256 + tn)*32 + pg];
        }
        #pragma unroll
        for (int q2 = 0; q2 < 4; q2++){
            const ulonglong2* x4 = (const ulonglong2*)sx[q2];
            const ulonglong2* h4 = (const ulonglong2*)sh[q2];
            ull a0=0,a1=0,b0=0,b1=0;
            #pragma unroll
            for (int k = 0; k < 8; k++){ ulonglong2 v=x4[k]; fma2(a0,wi[2*k],v.x); fma2(a1,wi[2*k+1],v.y); }
            #pragma unroll
            for (int k = 0; k < 16; k++){ ulonglong2 v=h4[k]; fma2(b0,wh[2*k],v.x); fma2(b1,wh[2*k+1],v.y); }
            sgi[q2][g] = hsum2(a0)+hsum2(a1)+bi;
            sgh[q2][g] = hsum2(b0)+hsum2(b1)+bh;
        }
        __syncthreads();
        if (g < 64){
            #pragma unroll
            for (int q2 = 0; q2 < 4; q2++){
                float r  = sigf(sgi[q2][g]+sgh[q2][g]);
                float z  = sigf(sgi[q2][64+g]+sgh[q2][64+g]);
                float nn = tanhf(sgi[q2][128+g]+r*sgh[q2][128+g]);
                float h  = (1.f-z)*nn + z*sh[q2][g];
                sh[q2][g] = h;
                obase[((size_t)q2*256 + t)*128 + g] = h;
            }
        }
    }
}

// ---- GRU layer 1 forward: 4 sequences per CTA, A/B role split ----
__global__ __launch_bounds__(384,1) void k_gru1f(
    const float* __restrict__ Wih, const float* __restrict__ Whh,
    const float* __restrict__ bih, const float* __restrict__ bhh)
{
    int n0 = blockIdx.x * 4;
    int tid = threadIdx.x;
    bool isA = tid < 192;
    int g = isA ? tid : tid - 192;
    __shared__ __align__(16) float sx[4][128];
    __shared__ __align__(16) float sh[4][64];
    __shared__ float sgi[4][192], sgh[4][192];

    ull w[64];
    if (isA){
        const ull* p = (const ull*)(Wih + (size_t)g*128);
        #pragma unroll
        for (int k = 0; k < 64; k++) w[k] = p[k];
    } else {
        const ull* p = (const ull*)(Whh + (size_t)g*64);
        #pragma unroll
        for (int k = 0; k < 32; k++) w[k] = p[k];
    }
    float bias = isA ? bih[g] : bhh[g];

    const float* xbase = g_h0 + (size_t)n0*256*128;   // layout (seq, t, 128)
    if (tid < 64){ sh[0][tid]=0.f; sh[1][tid]=0.f; sh[2][tid]=0.f; sh[3][tid]=0.f; }
    int q0 = tid >> 7, j0 = tid & 127;                 // lanes cover seqs 0..2
    float xr0 = xbase[(size_t)q0*32768 + j0];
    float xr1 = (tid < 128) ? xbase[3UL*32768 + tid] : 0.f;  // seq 3

    for (int t = 0; t < 256; t++){
        sx[q0][j0] = xr0;
        if (tid < 128) sx[3][tid] = xr1;
        __syncthreads();
        if (t < 255){
            xr0 = xbase[(size_t)q0*32768 + (size_t)(t+1)*128 + j0];
            if (tid < 128) xr1 = xbase[3UL*32768 + (size_t)(t+1)*128 + tid];
        }
        #pragma unroll
        for (int q2 = 0; q2 < 4; q2++){
            ull a0 = 0, a1 = 0;
            if (isA){
                const ulonglong2* v4 = (const ulonglong2*)sx[q2];
                #pragma unroll
                for (int k = 0; k < 32; k++){ ulonglong2 v = v4[k]; fma2(a0, w[2*k], v.x); fma2(a1, w[2*k+1], v.y); }
                sgi[q2][g] = hsum2(a0) + hsum2(a1) + bias;
            } else {
                const ulonglong2* v4 = (const ulonglong2*)sh[q2];
                #pragma unroll
                for (int k = 0; k < 16; k++){ ulonglong2 v = v4[k]; fma2(a0, w[2*k], v.x); fma2(a1, w[2*k+1], v.y); }
                sgh[q2][g] = hsum2(a0) + hsum2(a1) + bias;
            }
        }
        __syncthreads();
        if (tid < 64){
            #pragma unroll
            for (int q2 = 0; q2 < 4; q2++){
                float r  = sigf(sgi[q2][tid] + sgh[q2][tid]);
                float z  = sigf(sgi[q2][64+tid] + sgh[q2][64+tid]);
                float nn = tanhf(sgi[q2][128+tid] + r*sgh[q2][128+tid]);
                float h  = (1.f - z)*nn + z*sh[q2][tid];
                sh[q2][tid] = h;
                if (t == 255) g_last[(n0+q2)*128 + tid] = h;
            }
        }
    }
}

__global__ __launch_bounds__(192,2) void k_gru1b(
    const float* __restrict__ Wih, const float* __restrict__ Whh,
    const float* __restrict__ bih, const float* __restrict__ bhh)
{
    int tid = threadIdx.x;
    __shared__ __align__(16) float sx[128];
    __shared__ float sgi[192];
    ull w[64];
    const ull* p = (const ull*)(Wih + 192UL*128 + (size_t)tid*128);
    #pragma unroll
    for (int k = 0; k < 64; k++) w[k] = p[k];
    float bias = bih[192 + tid];

    for (int it = 0; it < 64; it++){
        int n = blockIdx.x*64 + it;
        if (tid < 128) sx[tid] = g_h0[((size_t)n*256 + 255)*128 + tid];
        __syncthreads();
        ull a0 = 0, a1 = 0;
        const ulonglong2* v4 = (const ulonglong2*)sx;
        #pragma unroll
        for (int k = 0; k < 32; k++){ ulonglong2 v = v4[k]; fma2(a0, w[2*k], v.x); fma2(a1, w[2*k+1], v.y); }
        sgi[tid] = hsum2(a0) + hsum2(a1) + bias;
        __syncthreads();
        if (tid < 64){
            float r  = sigf(sgi[tid]      + bhh[192 + tid]);
            float z  = sigf(sgi[64 + tid] + bhh[192 + 64 + tid]);
            float nn = tanhf(sgi[128+tid] + r * bhh[192 + 128 + tid]);
            g_last[n*128 + 64 + tid] = (1.f - z)*nn;
        }
    }
}

__global__ __launch_bounds__(128) void k_head(
    const float* __restrict__ pool_W, const float* __restrict__ pool_b,
    const float* __restrict__ mu_W, const float* __restrict__ mu_b,
    const float* __restrict__ logv_W, const float* __restrict__ logv_b,
    const float* __restrict__ dec_W, const float* __restrict__ dec_b,
    const float* __restrict__ lstm_Wih, const float* __restrict__ lstm_bih,
    const float* __restrict__ lstm_bhh,
    float* __restrict__ out)
{
    int b = blockIdx.x, tid = threadIdx.x;
    __shared__ float slast[128], shp[32], smu[32], sdh[64];
    float s = 0.f;
    for (int c = 0; c < 64; c++) s += g_last[(b*64 + c)*128 + tid];
    slast[tid] = s * (1.f/64.f);
    __syncthreads();
    if (tid < 32){
        float acc = pool_b[tid];
        for (int k = 0; k < 128; k++) acc += pool_W[tid*128 + k] * slast[k];
        shp[tid] = fmaxf(acc, 0.f);
    }
    __syncthreads();
    if (tid < 32){
        float acc = mu_b[tid];
        for (int k = 0; k < 32; k++) acc += mu_W[tid*32 + k] * shp[k];
        smu[tid] = acc;
        out[64UL*256*64 + b*32 + tid] = acc;
    } else if (tid < 64){
        int j = tid - 32;
        float acc = logv_b[j];
        for (int k = 0; k < 32; k++) acc += logv_W[j*32 + k] * shp[k];
        out[64UL*256*64 + 2048 + b*32 + j] = acc;
    }
    __syncthreads();
    if (tid < 64){
        float acc = dec_b[tid];
        for (int k = 0; k < 32; k++) acc += dec_W[tid*32 + k] * smu[k];
        sdh[tid] = fmaxf(acc, 0.f);
    }
    __syncthreads();
    for (int gate = tid; gate < 256; gate += 128){
        float acc = lstm_bih[gate] + lstm_bhh[gate];
        for (int k = 0; k < 64; k++) acc += lstm_Wih[gate*64 + k] * sdh[k];
        g_dxg[b*256 + gate] = acc;
    }
}

__global__ __launch_bounds__(256,1) void k_lstm1(const float* __restrict__ Whh)
{
    int b = blockIdx.x, tid = threadIdx.x;
    __shared__ __align__(16) float sh[64];
    __shared__ float sg[256];
    ull w[32];
    const ull* p = (const ull*)(Whh + (size_t)tid*64);
    #pragma unroll
    for (int k = 0; k < 32; k++) w[k] = p[k];
    float dxg = g_dxg[b*256 + tid];
    if (tid < 64) sh[tid] = 0.f;
    float c = 0.f;
    for (int t = 0; t < 256; t++){
        __syncthreads();
        ull a0 = 0, a1 = 0;
        const ulonglong2* v4 = (const ulonglong2*)sh;
        #pragma unroll
        for (int k = 0; k < 16; k++){ ulonglong2 v = v4[k]; fma2(a0, w[2*k], v.x); fma2(a1, w[2*k+1], v.y); }
        sg[tid] = hsum2(a0) + hsum2(a1) + dxg;
        __syncthreads();
        if (tid < 64){
            float i_ = sigf(sg[tid]), f_ = sigf(sg[64+tid]);
            float gg = tanhf(sg[128+tid]), o_ = sigf(sg[192+tid]);
            c = f_*c + i_*gg;
            float h = o_*tanhf(c);
            sh[tid] = h;
            g_h1d[((size_t)b*256 + t)*64 + tid] = h;
        }
    }
}

__global__ __launch_bounds__(256,1) void k_lstm2(
    const float* __restrict__ Wih, const float* __restrict__ Whh,
    const float* __restrict__ bih, const float* __restrict__ bhh,
    const float* __restrict__ out_W, const float* __restrict__ out_b,
    float* __restrict__ out)
{
    int b = blockIdx.x, tid = threadIdx.x;
    __shared__ __align__(16) float sx[64];
    __shared__ __align__(16) float sh[64];
    __shared__ float sg[256];
    __shared__ float soW[64*64];
    for (int i = tid; i < 4096; i += 256){ int c = i >> 6, k = i & 63; soW[k*64 + c] = out_W[i]; }
    ull wi[32], wh[32];
    const ull* p = (const ull*)(Wih + 256UL*64 + (size_t)tid*64);
    const ull* q = (const ull*)(Whh + 256UL*64 + (size_t)tid*64);
    #pragma unroll
    for (int k = 0; k < 32; k++){ wi[k] = p[k]; wh[k] = q[k]; }
    float bias = bih[256 + tid] + bhh[256 + tid];
    if (tid < 64) sh[tid] = 0.f;
    float c = 0.f;
    float ob = (tid >= 64 && tid < 128) ? out_b[tid - 64] : 0.f;
    const float* xb = g_h1d + (size_t)b*256*64;
    for (int t = 0; t < 256; t++){
        if (tid < 64) sx[tid] = xb[t*64 + tid];
        __syncthreads();
        ull a0 = 0, a1 = 0;
        const ulonglong2* x4 = (const ulonglong2*)sx;
        const ulonglong2* h4 = (const ulonglong2*)sh;
        #pragma unroll
        for (int k = 0; k < 16; k++){ ulonglong2 v = x4[k]; fma2(a0, wi[2*k], v.x); fma2(a1, wi[2*k+1], v.y); }
        #pragma unroll
        for (int k = 0; k < 16; k++){ ulonglong2 v = h4[k]; fma2(a0, wh[2*k], v.x); fma2(a1, wh[2*k+1], v.y); }
        sg[tid] = hsum2(a0) + hsum2(a1) + bias;
        __syncthreads();
        if (tid < 64){
            float i_ = sigf(sg[tid]), f_ = sigf(sg[64+tid]);
            float gg = tanhf(sg[128+tid]), o_ = sigf(sg[192+tid]);
            c = f_*c + i_*gg;
            sh[tid] = o_*tanhf(c);
        }
        __syncthreads();
        if (tid >= 64 && tid < 128){
            int cc = tid - 64;
            float acc = ob;
            #pragma unroll 8
            for (int k = 0; k < 64; k++) acc += soW[k*64 + cc] * sh[k];
            out[((size_t)b*256 + t)*64 + cc] = acc;
        }
    }
}

extern "C" void kernel_launch(void* const* d_in, const int* in_sizes, int n_in,
                              void* d_out, int out_size)
{
    const float* x      = (const float*)d_in[0];
    const float* adj1   = (const float*)d_in[1];
    const float* W1     = (const float*)d_in[2];
    const float* b1     = (const float*)d_in[3];
    const float* adj2   = (const float*)d_in[4];
    const float* W2     = (const float*)d_in[5];
    const float* b2     = (const float*)d_in[6];
    const float* ln_g   = (const float*)d_in[7];
    const float* ln_b   = (const float*)d_in[8];
    const float* g0Wih  = (const float*)d_in[9];
    const float* g0Whh  = (const float*)d_in[10];
    const float* g0bih  = (const float*)d_in[11];
    const float* g0bhh  = (const float*)d_in[12];
    const float* g1Wih  = (const float*)d_in[13];
    const float* g1Whh  = (const float*)d_in[14];
    const float* g1bih  = (const float*)d_in[15];
    const float* g1bhh  = (const float*)d_in[16];
    const float* pool_W = (const float*)d_in[17];
    const float* pool_b = (const float*)d_in[18];
    const float* mu_W   = (const float*)d_in[19];
    const float* mu_b   = (const float*)d_in[20];
    const float* logv_W = (const float*)d_in[21];
    const float* logv_b = (const float*)d_in[22];
    const float* dec_W  = (const float*)d_in[23];
    const float* dec_b  = (const float*)d_in[24];
    const float* lWih   = (const float*)d_in[25];
    const float* lWhh   = (const float*)d_in[26];
    const float* lbih   = (const float*)d_in[27];
    const float* lbhh   = (const float*)d_in[28];
    const float* out_W  = (const float*)d_in[29];
    const float* out_b  = (const float*)d_in[30];
    float* out = (float*)d_out;

    k_softmax<<<1, 64>>>(adj1, adj2);
    k_gnn<<<16384, 256>>>(x, W1, b1, W2, b2, ln_g, ln_b);
    k_gru0<<<dim3(1024, 2), 192>>>(g0Wih, g0Whh, g0bih, g0bhh);
    k_gru1f<<<1024, 384>>>(g1Wih, g1Whh, g1bih, g1bhh);
    k_gru1b<<<64, 192>>>(g1Wih, g1Whh, g1bih, g1bhh);
    k_head<<<64, 128>>>(pool_W, pool_b, mu_W, mu_b, logv_W, logv_b,
                        dec_W, dec_b, lWih, lbih, lbhh, out);
    k_lstm1<<<64, 256>>>(lWhh);
    k_lstm2<<<64, 256>>>(lWih, lWhh, lbih, lbhh, out_W, out_b, out);
}

// round 7
// speedup vs baseline: 1.4314x; 1.2801x over previous
#include <cuda_runtime.h>
#include <cuda_bf16.h>
#include <cstdint>
#include <math.h>

typedef unsigned long long ull;

__device__ float g_A1[64*64];
__device__ float g_A2[64*64];
__device__ float g_henc[4096UL*256*32];
__device__ __nv_bfloat16 g_h0H[4096UL*256*128];
__device__ __nv_bfloat16 g_h0L[4096UL*256*128];
__device__ __nv_bfloat16 g_WThi[192*128];
__device__ __nv_bfloat16 g_WTlo[192*128];
__device__ float g_xg1[4096UL*256*192];
__device__ float g_last[4096*128];
__device__ float g_dxg[64*256];
__device__ float g_h1d[64UL*256*64];

__device__ __forceinline__ void fma2(ull &acc, ull a, ull b){
    asm("fma.rn.f32x2 %0, %1, %2, %0;" : "+l"(acc) : "l"(a), "l"(b));
}
__device__ __forceinline__ float hsum2(ull a){
    float lo, hi; asm("mov.b64 {%0,%1}, %2;" : "=f"(lo), "=f"(hi) : "l"(a));
    return lo + hi;
}
__device__ __forceinline__ float sigf(float x){ return 1.f/(1.f + expf(-x)); }

__global__ void k_softmax(const float* __restrict__ adj1, const float* __restrict__ adj2){
    int i = threadIdx.x;
    for (int w = 0; w < 2; w++){
        const float* a = w ? adj2 : adj1;
        float* o = w ? g_A2 : g_A1;
        float mx = -1e30f;
        for (int j = 0; j < 64; j++) mx = fmaxf(mx, a[i*64+j]);
        float s = 0.f;
        for (int j = 0; j < 64; j++) s += expf(a[i*64+j] - mx);
        float inv = 1.f / s;
        for (int j = 0; j < 64; j++) o[i*64+j] = expf(a[i*64+j] - mx) * inv;
    }
}

__global__ void k_prepW(const float* __restrict__ W){
    for (int i = threadIdx.x; i < 24576; i += 256){
        float v = W[i];
        __nv_bfloat16 hi = __float2bfloat16(v);
        __nv_bfloat16 lo = __float2bfloat16(v - __bfloat162float(hi));
        g_WThi[i] = hi; g_WTlo[i] = lo;
    }
}

__global__ __launch_bounds__(256) void k_gnn(
    const float* __restrict__ x,
    const float* __restrict__ W1, const float* __restrict__ b1,
    const float* __restrict__ W2, const float* __restrict__ b2,
    const float* __restrict__ lng, const float* __restrict__ lnb)
{
    int bt = blockIdx.x;
    int b = bt >> 8, t = bt & 255;
    int tid = threadIdx.x;

    __shared__ float sA2[64*65];
    __shared__ float sW2t[1024];
    __shared__ __align__(16) float sx[64];
    __shared__ float s1[64];
    __shared__ __align__(16) float sh1[2048];
    __shared__ __align__(16) float sagg[2048];
    __shared__ float sh2[64*33];
    __shared__ float sW1[32], sb1[32], sb2[32], slg[32], slb[32];
    __shared__ float smean[64], srstd[64];

    for (int i = tid; i < 4096; i += 256) sA2[(i>>6)*65 + (i&63)] = g_A2[i];
    for (int i = tid; i < 1024; i += 256){ int gp = i>>5, k = i&31; sW2t[k*32+gp] = W2[i]; }
    if (tid < 64) sx[tid] = x[(size_t)bt*64 + tid];
    if (tid < 32){ sW1[tid]=W1[tid]; sb1[tid]=b1[tid]; sb2[tid]=b2[tid]; slg[tid]=lng[tid]; slb[tid]=lnb[tid]; }
    __syncthreads();

    if (tid < 64){
        float s = 0.f; const float* a = g_A1 + tid*64;
        #pragma unroll 8
        for (int j = 0; j < 64; j++) s += a[j]*sx[j];
        s1[tid] = s;
    }
    __syncthreads();
    for (int i = tid; i < 2048; i += 256){ int j = i>>5, g = i&31; sh1[i] = fmaxf(sW1[g]*s1[j] + sb1[g], 0.f); }
    __syncthreads();
    {
        int i = tid >> 2, g0 = (tid & 3) * 8;
        float4 a0 = {0,0,0,0}, a1 = {0,0,0,0};
        #pragma unroll 4
        for (int j = 0; j < 64; j++){
            float a = sA2[i*65 + j];
            float4 h0 = *(const float4*)(sh1 + j*32 + g0);
            float4 h1 = *(const float4*)(sh1 + j*32 + g0 + 4);
            a0.x += a*h0.x; a0.y += a*h0.y; a0.z += a*h0.z; a0.w += a*h0.w;
            a1.x += a*h1.x; a1.y += a*h1.y; a1.z += a*h1.z; a1.w += a*h1.w;
        }
        *(float4*)(sagg + i*32 + g0)     = a0;
        *(float4*)(sagg + i*32 + g0 + 4) = a1;
    }
    __syncthreads();
    #pragma unroll
    for (int q = 0; q < 8; q++){
        int idx = tid + (q << 8);
        int i = idx >> 5, gp = idx & 31;
        float acc = sb2[gp];
        #pragma unroll 8
        for (int k = 0; k < 32; k++) acc += sagg[i*32 + k] * sW2t[k*32 + gp];
        sh2[i*33 + gp] = fmaxf(acc, 0.f);
    }
    __syncthreads();
    if (tid < 64){
        float m = 0.f;
        for (int g = 0; g < 32; g++) m += sh2[tid*33 + g];
        m *= (1.f/32.f);
        float v = 0.f;
        for (int g = 0; g < 32; g++){ float d = sh2[tid*33 + g] - m; v += d*d; }
        v *= (1.f/32.f);
        smean[tid] = m; srstd[tid] = rsqrtf(v + 1e-5f);
    }
    __syncthreads();
    for (int idx = tid; idx < 2048; idx += 256){
        int i = idx >> 5, g = idx & 31;
        float val = (sh2[i*33 + g] - smean[i]) * srstd[i] * slg[g] + slb[g];
        g_henc[(((size_t)b*64 + i)*256 + t)*32 + g] = val;
    }
}

// ---- BiGRU layer 0: 8 sequences per CTA, h out as bf16 hi/lo ----
__global__ __launch_bounds__(192,2) void k_gru0(
    const float* __restrict__ Wih, const float* __restrict__ Whh,
    const float* __restrict__ bih, const float* __restrict__ bhh)
{
    int n0 = blockIdx.x * 8, dir = blockIdx.y;
    int g = threadIdx.x;
    __shared__ __align__(16) float sx[8][32];
    __shared__ __align__(16) float sh[8][64];
    __shared__ float sgi[8][192], sgh[8][192];

    ull wi[16], wh[32];
    {
        const ull* p = (const ull*)(Wih + ((size_t)dir*192 + g)*32);
        #pragma unroll
        for (int k = 0; k < 16; k++) wi[k] = p[k];
        const ull* q = (const ull*)(Whh + ((size_t)dir*192 + g)*64);
        #pragma unroll
        for (int k = 0; k < 32; k++) wh[k] = q[k];
    }
    float bi = bih[dir*192+g], bh = bhh[dir*192+g];

    const float* xb = g_henc + (size_t)n0*8192;
    for (int u = g; u < 512; u += 192) sh[u>>6][u&63] = 0.f;

    int q0 = g >> 5, p0 = g & 31;
    int t0 = dir ? 255 : 0;
    float xr0 = xb[(size_t)q0*8192 + t0*32 + p0];
    float xr1 = (g < 64) ? xb[(size_t)(6 + (g>>5))*8192 + t0*32 + (g&31)] : 0.f;

    for (int s = 0; s < 256; s++){
        int t = dir ? 255 - s : s;
        sx[q0][p0] = xr0;
        if (g < 64) sx[6 + (g>>5)][g&31] = xr1;
        __syncthreads();
        if (s < 255){
            int tn = dir ? 254 - s : s + 1;
            xr0 = xb[(size_t)q0*8192 + tn*32 + p0];
            if (g < 64) xr1 = xb[(size_t)(6 + (g>>5))*8192 + tn*32 + (g&31)];
        }
        #pragma unroll
        for (int q2 = 0; q2 < 8; q2++){
            const ulonglong2* x4 = (const ulonglong2*)sx[q2];
            const ulonglong2* h4 = (const ulonglong2*)sh[q2];
            ull a0=0,a1=0,b0=0,b1=0;
            #pragma unroll
            for (int k = 0; k < 8; k++){ ulonglong2 v=x4[k]; fma2(a0,wi[2*k],v.x); fma2(a1,wi[2*k+1],v.y); }
            #pragma unroll
            for (int k = 0; k < 16; k++){ ulonglong2 v=h4[k]; fma2(b0,wh[2*k],v.x); fma2(b1,wh[2*k+1],v.y); }
            sgi[q2][g] = hsum2(a0)+hsum2(a1)+bi;
            sgh[q2][g] = hsum2(b0)+hsum2(b1)+bh;
        }
        __syncthreads();
        for (int u = g; u < 512; u += 192){
            int q2 = u >> 6, hh = u & 63;
            float r  = sigf(sgi[q2][hh]+sgh[q2][hh]);
            float z  = sigf(sgi[q2][64+hh]+sgh[q2][64+hh]);
            float nn = tanhf(sgi[q2][128+hh]+r*sgh[q2][128+hh]);
            float h  = (1.f-z)*nn + z*sh[q2][hh];
            sh[q2][hh] = h;
            __nv_bfloat16 hi = __float2bfloat16(h);
            __nv_bfloat16 lo = __float2bfloat16(h - __bfloat162float(hi));
            size_t idx = ((size_t)(n0+q2)*256 + t)*128 + dir*64 + hh;
            g_h0H[idx] = hi; g_h0L[idx] = lo;
        }
        __syncthreads();
    }
}

// ---- mma.sync GEMM: xg1 = h0 @ Wih1^T (M=1M, N=192, K=128), 3-term split bf16 ----
__global__ __launch_bounds__(256,2) void k_xproj1(){
    __shared__ uint32_t sA[2][16*68];
    int tid = threadIdx.x;
    int w = tid >> 5, lane = tid & 31;
    int g = lane >> 2, tig = lane & 3;
    size_t Rbase = (size_t)blockIdx.x * 1024;

    uint32_t bh[3][8][2];
    #pragma unroll
    for (int nt = 0; nt < 3; nt++){
        int n = w*24 + nt*8 + g;
        const uint32_t* wp = (const uint32_t*)g_WThi + n*64;
        #pragma unroll
        for (int ks = 0; ks < 8; ks++){
            bh[nt][ks][0] = wp[ks*8 + tig];
            bh[nt][ks][1] = wp[ks*8 + 4 + tig];
        }
    }
    const uint32_t* blo = (const uint32_t*)g_WTlo;
    const uint32_t* h0Hu = (const uint32_t*)g_h0H;
    const uint32_t* h0Lu = (const uint32_t*)g_h0L;

    for (int mt = 0; mt < 64; mt++){
        size_t R = Rbase + mt*16;
        __syncthreads();
        for (int i = tid; i < 1024; i += 256){
            int row = i >> 6, c = i & 63;
            sA[0][row*68 + c] = h0Hu[(R+row)*64 + c];
            sA[1][row*68 + c] = h0Lu[(R+row)*64 + c];
        }
        __syncthreads();
        float acc[3][4];
        #pragma unroll
        for (int nt=0;nt<3;nt++){ acc[nt][0]=0.f; acc[nt][1]=0.f; acc[nt][2]=0.f; acc[nt][3]=0.f; }
        #pragma unroll
        for (int term = 0; term < 3; term++){
            const uint32_t* As = sA[term == 1 ? 1 : 0];
            #pragma unroll
            for (int ks = 0; ks < 8; ks++){
                uint32_t a0 = As[g*68 + ks*8 + tig];
                uint32_t a1 = As[(g+8)*68 + ks*8 + tig];
                uint32_t a2 = As[g*68 + ks*8 + 4 + tig];
                uint32_t a3 = As[(g+8)*68 + ks*8 + 4 + tig];
                #pragma unroll
                for (int nt = 0; nt < 3; nt++){
                    uint32_t b0, b1;
                    if (term < 2){ b0 = bh[nt][ks][0]; b1 = bh[nt][ks][1]; }
                    else {
                        int n = w*24 + nt*8 + g;
                        b0 = __ldg(blo + n*64 + ks*8 + tig);
                        b1 = __ldg(blo + n*64 + ks*8 + 4 + tig);
                    }
                    asm volatile(
                        "mma.sync.aligned.m16n8k16.row.col.f32.bf16.bf16.f32 "
                        "{%0,%1,%2,%3}, {%4,%5,%6,%7}, {%8,%9}, {%0,%1,%2,%3};"
                        : "+f"(acc[nt][0]), "+f"(acc[nt][1]), "+f"(acc[nt][2]), "+f"(acc[nt][3])
                        : "r"(a0), "r"(a1), "r"(a2), "r"(a3), "r"(b0), "r"(b1));
                }
            }
        }
        #pragma unroll
        for (int nt = 0; nt < 3; nt++){
            int col = w*24 + nt*8 + tig*2;
            float2 v0 = make_float2(acc[nt][0], acc[nt][1]);
            float2 v1 = make_float2(acc[nt][2], acc[nt][3]);
            *(float2*)(g_xg1 + (R+g)*192 + col) = v0;
            *(float2*)(g_xg1 + (R+g+8)*192 + col) = v1;
        }
    }
}

// ---- GRU layer 1 fwd, hidden recurrence only, 8 seqs per CTA ----
__global__ __launch_bounds__(192,2) void k_gru1h(
    const float* __restrict__ Whh, const float* __restrict__ bih, const float* __restrict__ bhh)
{
    int n0 = blockIdx.x * 8;
    int g = threadIdx.x;
    __shared__ __align__(16) float sh[8][64];
    __shared__ float sgi[8][192], sgh[8][192];

    ull wh[32];
    const ull* p = (const ull*)(Whh + (size_t)g*64);
    #pragma unroll
    for (int k = 0; k < 32; k++) wh[k] = p[k];
    float bi = bih[g], bh = bhh[g];

    for (int u = g; u < 512; u += 192) sh[u>>6][u&63] = 0.f;
    __syncthreads();

    float xr[8];
    #pragma unroll
    for (int q = 0; q < 8; q++) xr[q] = g_xg1[((size_t)(n0+q)*256)*192 + g];

    for (int t = 0; t < 256; t++){
        #pragma unroll
        for (int q = 0; q < 8; q++) sgi[q][g] = xr[q] + bi;
        if (t < 255){
            #pragma unroll
            for (int q = 0; q < 8; q++) xr[q] = g_xg1[((size_t)(n0+q)*256 + t + 1)*192 + g];
        }
        #pragma unroll
        for (int q = 0; q < 8; q++){
            const ulonglong2* h4 = (const ulonglong2*)sh[q];
            ull b0 = 0, b1 = 0;
            #pragma unroll
            for (int k = 0; k < 16; k++){ ulonglong2 v = h4[k]; fma2(b0, wh[2*k], v.x); fma2(b1, wh[2*k+1], v.y); }
            sgh[q][g] = hsum2(b0) + hsum2(b1) + bh;
        }
        __syncthreads();
        for (int u = g; u < 512; u += 192){
            int q = u >> 6, hh = u & 63;
            float r  = sigf(sgi[q][hh] + sgh[q][hh]);
            float z  = sigf(sgi[q][64+hh] + sgh[q][64+hh]);
            float nn = tanhf(sgi[q][128+hh] + r*sgh[q][128+hh]);
            float h  = (1.f - z)*nn + z*sh[q][hh];
            sh[q][hh] = h;
            if (t == 255) g_last[(n0+q)*128 + hh] = h;
        }
        __syncthreads();
    }
}

__global__ __launch_bounds__(192,2) void k_gru1b(
    const float* __restrict__ Wih, const float* __restrict__ Whh,
    const float* __restrict__ bih, const float* __restrict__ bhh)
{
    int tid = threadIdx.x;
    __shared__ __align__(16) float sx[128];
    __shared__ float sgi[192];
    ull w[64];
    const ull* p = (const ull*)(Wih + 192UL*128 + (size_t)tid*128);
    #pragma unroll
    for (int k = 0; k < 64; k++) w[k] = p[k];
    float bias = bih[192 + tid];

    for (int it = 0; it < 64; it++){
        int n = blockIdx.x*64 + it;
        if (tid < 128){
            size_t idx = ((size_t)n*256 + 255)*128 + tid;
            sx[tid] = __bfloat162float(g_h0H[idx]) + __bfloat162float(g_h0L[idx]);
        }
        __syncthreads();
        ull a0 = 0, a1 = 0;
        const ulonglong2* v4 = (const ulonglong2*)sx;
        #pragma unroll
        for (int k = 0; k < 32; k++){ ulonglong2 v = v4[k]; fma2(a0, w[2*k], v.x); fma2(a1, w[2*k+1], v.y); }
        sgi[tid] = hsum2(a0) + hsum2(a1) + bias;
        __syncthreads();
        if (tid < 64){
            float r  = sigf(sgi[tid]      + bhh[192 + tid]);
            float z  = sigf(sgi[64 + tid] + bhh[192 + 64 + tid]);
            float nn = tanhf(sgi[128+tid] + r * bhh[192 + 128 + tid]);
            g_last[n*128 + 64 + tid] = (1.f - z)*nn;
        }
    }
}

__global__ __launch_bounds__(128) void k_head(
    const float* __restrict__ pool_W, const float* __restrict__ pool_b,
    const float* __restrict__ mu_W, const float* __restrict__ mu_b,
    const float* __restrict__ logv_W, const float* __restrict__ logv_b,
    const float* __restrict__ dec_W, const float* __restrict__ dec_b,
    const float* __restrict__ lstm_Wih, const float* __restrict__ lstm_bih,
    const float* __restrict__ lstm_bhh,
    float* __restrict__ out)
{
    int b = blockIdx.x, tid = threadIdx.x;
    __shared__ float slast[128], shp[32], smu[32], sdh[64];
    float s = 0.f;
    for (int c = 0; c < 64; c++) s += g_last[(b*64 + c)*128 + tid];
    slast[tid] = s * (1.f/64.f);
    __syncthreads();
    if (tid < 32){
        float acc = pool_b[tid];
        for (int k = 0; k < 128; k++) acc += pool_W[tid*128 + k] * slast[k];
        shp[tid] = fmaxf(acc, 0.f);
    }
    __syncthreads();
    if (tid < 32){
        float acc = mu_b[tid];
        for (int k = 0; k < 32; k++) acc += mu_W[tid*32 + k] * shp[k];
        smu[tid] = acc;
        out[64UL*256*64 + b*32 + tid] = acc;
    } else if (tid < 64){
        int j = tid - 32;
        float acc = logv_b[j];
        for (int k = 0; k < 32; k++) acc += logv_W[j*32 + k] * shp[k];
        out[64UL*256*64 + 2048 + b*32 + j] = acc;
    }
    __syncthreads();
    if (tid < 64){
        float acc = dec_b[tid];
        for (int k = 0; k < 32; k++) acc += dec_W[tid*32 + k] * smu[k];
        sdh[tid] = fmaxf(acc, 0.f);
    }
    __syncthreads();
    for (int gate = tid; gate < 256; gate += 128){
        float acc = lstm_bih[gate] + lstm_bhh[gate];
        for (int k = 0; k < 64; k++) acc += lstm_Wih[gate*64 + k] * sdh[k];
        g_dxg[b*256 + gate] = acc;
    }
}

__global__ __launch_bounds__(256,1) void k_lstm1(const float* __restrict__ Whh)
{
    int b = blockIdx.x, tid = threadIdx.x;
    __shared__ __align__(16) float sh[64];
    __shared__ float sg[256];
    ull w[32];
    const ull* p = (const ull*)(Whh + (size_t)tid*64);
    #pragma unroll
    for (int k = 0; k < 32; k++) w[k] = p[k];
    float dxg = g_dxg[b*256 + tid];
    if (tid < 64) sh[tid] = 0.f;
    float c = 0.f;
    for (int t = 0; t < 256; t++){
        __syncthreads();
        ull a0 = 0, a1 = 0;
        const ulonglong2* v4 = (const ulonglong2*)sh;
        #pragma unroll
        for (int k = 0; k < 16; k++){ ulonglong2 v = v4[k]; fma2(a0, w[2*k], v.x); fma2(a1, w[2*k+1], v.y); }
        sg[tid] = hsum2(a0) + hsum2(a1) + dxg;
        __syncthreads();
        if (tid < 64){
            float i_ = sigf(sg[tid]), f_ = sigf(sg[64+tid]);
            float gg = tanhf(sg[128+tid]), o_ = sigf(sg[192+tid]);
            c = f_*c + i_*gg;
            float h = o_*tanhf(c);
            sh[tid] = h;
            g_h1d[((size_t)b*256 + t)*64 + tid] = h;
        }
    }
}

__global__ __launch_bounds__(256,1) void k_lstm2(
    const float* __restrict__ Wih, const float* __restrict__ Whh,
    const float* __restrict__ bih, const float* __restrict__ bhh,
    const float* __restrict__ out_W, const float* __restrict__ out_b,
    float* __restrict__ out)
{
    int b = blockIdx.x, tid = threadIdx.x;
    __shared__ __align__(16) float sx[64];
    __shared__ __align__(16) float sh[64];
    __shared__ float sg[256];
    __shared__ float soW[64*64];
    for (int i = tid; i < 4096; i += 256){ int c = i >> 6, k = i & 63; soW[k*64 + c] = out_W[i]; }
    ull wi[32], wh[32];
    const ull* p = (const ull*)(Wih + 256UL*64 + (size_t)tid*64);
    const ull* q = (const ull*)(Whh + 256UL*64 + (size_t)tid*64);
    #pragma unroll
    for (int k = 0; k < 32; k++){ wi[k] = p[k]; wh[k] = q[k]; }
    float bias = bih[256 + tid] + bhh[256 + tid];
    if (tid < 64) sh[tid] = 0.f;
    float c = 0.f;
    float ob = (tid >= 64 && tid < 128) ? out_b[tid - 64] : 0.f;
    const float* xb = g_h1d + (size_t)b*256*64;
    for (int t = 0; t < 256; t++){
        if (tid < 64) sx[tid] = xb[t*64 + tid];
        __syncthreads();
        ull a0 = 0, a1 = 0;
        const ulonglong2* x4 = (const ulonglong2*)sx;
        const ulonglong2* h4 = (const ulonglong2*)sh;
        #pragma unroll
        for (int k = 0; k < 16; k++){ ulonglong2 v = x4[k]; fma2(a0, wi[2*k], v.x); fma2(a1, wi[2*k+1], v.y); }
        #pragma unroll
        for (int k = 0; k < 16; k++){ ulonglong2 v = h4[k]; fma2(a0, wh[2*k], v.x); fma2(a1, wh[2*k+1], v.y); }
        sg[tid] = hsum2(a0) + hsum2(a1) + bias;
        __syncthreads();
        if (tid < 64){
            float i_ = sigf(sg[tid]), f_ = sigf(sg[64+tid]);
            float gg = tanhf(sg[128+tid]), o_ = sigf(sg[192+tid]);
            c = f_*c + i_*gg;
            sh[tid] = o_*tanhf(c);
        }
        __syncthreads();
        if (tid >= 64 && tid < 128){
            int cc = tid - 64;
            float acc = ob;
            #pragma unroll 8
            for (int k = 0; k < 64; k++) acc += soW[k*64 + cc] * sh[k];
            out[((size_t)b*256 + t)*64 + cc] = acc;
        }
    }
}

extern "C" void kernel_launch(void* const* d_in, const int* in_sizes, int n_in,
                              void* d_out, int out_size)
{
    const float* x      = (const float*)d_in[0];
    const float* adj1   = (const float*)d_in[1];
    const float* W1     = (const float*)d_in[2];
    const float* b1     = (const float*)d_in[3];
    const float* adj2   = (const float*)d_in[4];
    const float* W2     = (const float*)d_in[5];
    const float* b2     = (const float*)d_in[6];
    const float* ln_g   = (const float*)d_in[7];
    const float* ln_b   = (const float*)d_in[8];
    const float* g0Wih  = (const float*)d_in[9];
    const float* g0Whh  = (const float*)d_in[10];
    const float* g0bih  = (const float*)d_in[11];
    const float* g0bhh  = (const float*)d_in[12];
    const float* g1Wih  = (const float*)d_in[13];
    const float* g1Whh  = (const float*)d_in[14];
    const float* g1bih  = (const float*)d_in[15];
    const float* g1bhh  = (const float*)d_in[16];
    const float* pool_W = (const float*)d_in[17];
    const float* pool_b = (const float*)d_in[18];
    const float* mu_W   = (const float*)d_in[19];
    const float* mu_b   = (const float*)d_in[20];
    const float* logv_W = (const float*)d_in[21];
    const float* logv_b = (const float*)d_in[22];
    const float* dec_W  = (const float*)d_in[23];
    const float* dec_b  = (const float*)d_in[24];
    const float* lWih   = (const float*)d_in[25];
    const float* lWhh   = (const float*)d_in[26];
    const float* lbih   = (const float*)d_in[27];
    const float* lbhh   = (const float*)d_in[28];
    const float* out_W  = (const float*)d_in[29];
    const float* out_b  = (const float*)d_in[30];
    float* out = (float*)d_out;

    k_softmax<<<1, 64>>>(adj1, adj2);
    k_prepW<<<1, 256>>>(g1Wih);
    k_gnn<<<16384, 256>>>(x, W1, b1, W2, b2, ln_g, ln_b);
    k_gru0<<<dim3(512, 2), 192>>>(g0Wih, g0Whh, g0bih, g0bhh);
    k_xproj1<<<1024, 256>>>();
    k_gru1h<<<512, 192>>>(g1Whh, g1bih, g1bhh);
    k_gru1b<<<64, 192>>>(g1Wih, g1Whh, g1bih, g1bhh);
    k_head<<<64, 128>>>(pool_W, pool_b, mu_W, mu_b, logv_W, logv_b,
                        dec_W, dec_b, lWih, lbih, lbhh, out);
    k_lstm1<<<64, 256>>>(lWhh);
    k_lstm2<<<64, 256>>>(lWih, lWhh, lbih, lbhh, out_W, out_b, out);
}

// round 8
// speedup vs baseline: 1.4386x; 1.0050x over previous
#include <cuda_runtime.h>
#include <cuda_bf16.h>
#include <cstdint>
#include <math.h>

typedef unsigned long long ull;

__device__ float g_A1[64*64];
__device__ float g_A2[64*64];
__device__ __nv_bfloat16 g_hencH[4096UL*256*32];
__device__ __nv_bfloat16 g_hencL[4096UL*256*32];
__device__ __nv_bfloat16 g_h0H[4096UL*256*128];
__device__ __nv_bfloat16 g_h0L[4096UL*256*128];
__device__ __nv_bfloat16 g_W1hi[192*128];
__device__ __nv_bfloat16 g_W1lo[192*128];
__device__ __nv_bfloat16 g_W0hi[384*32];
__device__ __nv_bfloat16 g_W0lo[384*32];
__device__ float g_xg0[2UL*4096*256*192];
__device__ float g_xg1[4096UL*256*192];
__device__ float g_last[4096*128];
__device__ float g_dxg[64*256];
__device__ float g_h1d[64UL*256*64];

__device__ __forceinline__ void fma2(ull &acc, ull a, ull b){
    asm("fma.rn.f32x2 %0, %1, %2, %0;" : "+l"(acc) : "l"(a), "l"(b));
}
__device__ __forceinline__ float hsum2(ull a){
    float lo, hi; asm("mov.b64 {%0,%1}, %2;" : "=f"(lo), "=f"(hi) : "l"(a));
    return lo + hi;
}
__device__ __forceinline__ float sigf(float x){ return 1.f/(1.f + expf(-x)); }

__global__ void k_softmax(const float* __restrict__ adj1, const float* __restrict__ adj2){
    int i = threadIdx.x;
    for (int w = 0; w < 2; w++){
        const float* a = w ? adj2 : adj1;
        float* o = w ? g_A2 : g_A1;
        float mx = -1e30f;
        for (int j = 0; j < 64; j++) mx = fmaxf(mx, a[i*64+j]);
        float s = 0.f;
        for (int j = 0; j < 64; j++) s += expf(a[i*64+j] - mx);
        float inv = 1.f / s;
        for (int j = 0; j < 64; j++) o[i*64+j] = expf(a[i*64+j] - mx) * inv;
    }
}

__global__ void k_prepW(const float* __restrict__ W1, const float* __restrict__ W0){
    for (int i = threadIdx.x; i < 24576; i += 256){
        float v = W1[i];
        __nv_bfloat16 hi = __float2bfloat16(v);
        g_W1hi[i] = hi; g_W1lo[i] = __float2bfloat16(v - __bfloat162float(hi));
    }
    for (int i = threadIdx.x; i < 12288; i += 256){
        float v = W0[i];
        __nv_bfloat16 hi = __float2bfloat16(v);
        g_W0hi[i] = hi; g_W0lo[i] = __float2bfloat16(v - __bfloat162float(hi));
    }
}

__global__ __launch_bounds__(256) void k_gnn(
    const float* __restrict__ x,
    const float* __restrict__ W1, const float* __restrict__ b1,
    const float* __restrict__ W2, const float* __restrict__ b2,
    const float* __restrict__ lng, const float* __restrict__ lnb)
{
    int bt = blockIdx.x;
    int b = bt >> 8, t = bt & 255;
    int tid = threadIdx.x;

    __shared__ float sA2[64*65];
    __shared__ float sW2t[1024];
    __shared__ __align__(16) float sx[64];
    __shared__ float s1[64];
    __shared__ __align__(16) float sh1[2048];
    __shared__ __align__(16) float sagg[2048];
    __shared__ float sh2[64*33];
    __shared__ float sW1[32], sb1[32], sb2[32], slg[32], slb[32];
    __shared__ float smean[64], srstd[64];

    for (int i = tid; i < 4096; i += 256) sA2[(i>>6)*65 + (i&63)] = g_A2[i];
    for (int i = tid; i < 1024; i += 256){ int gp = i>>5, k = i&31; sW2t[k*32+gp] = W2[i]; }
    if (tid < 64) sx[tid] = x[(size_t)bt*64 + tid];
    if (tid < 32){ sW1[tid]=W1[tid]; sb1[tid]=b1[tid]; sb2[tid]=b2[tid]; slg[tid]=lng[tid]; slb[tid]=lnb[tid]; }
    __syncthreads();

    if (tid < 64){
        float s = 0.f; const float* a = g_A1 + tid*64;
        #pragma unroll 8
        for (int j = 0; j < 64; j++) s += a[j]*sx[j];
        s1[tid] = s;
    }
    __syncthreads();
    for (int i = tid; i < 2048; i += 256){ int j = i>>5, g = i&31; sh1[i] = fmaxf(sW1[g]*s1[j] + sb1[g], 0.f); }
    __syncthreads();
    {
        int i = tid >> 2, g0 = (tid & 3) * 8;
        float4 a0 = {0,0,0,0}, a1 = {0,0,0,0};
        #pragma unroll 4
        for (int j = 0; j < 64; j++){
            float a = sA2[i*65 + j];
            float4 h0 = *(const float4*)(sh1 + j*32 + g0);
            float4 h1 = *(const float4*)(sh1 + j*32 + g0 + 4);
            a0.x += a*h0.x; a0.y += a*h0.y; a0.z += a*h0.z; a0.w += a*h0.w;
            a1.x += a*h1.x; a1.y += a*h1.y; a1.z += a*h1.z; a1.w += a*h1.w;
        }
        *(float4*)(sagg + i*32 + g0)     = a0;
        *(float4*)(sagg + i*32 + g0 + 4) = a1;
    }
    __syncthreads();
    #pragma unroll
    for (int q = 0; q < 8; q++){
        int idx = tid + (q << 8);
        int i = idx >> 5, gp = idx & 31;
        float acc = sb2[gp];
        #pragma unroll 8
        for (int k = 0; k < 32; k++) acc += sagg[i*32 + k] * sW2t[k*32 + gp];
        sh2[i*33 + gp] = fmaxf(acc, 0.f);
    }
    __syncthreads();
    if (tid < 64){
        float m = 0.f;
        for (int g = 0; g < 32; g++) m += sh2[tid*33 + g];
        m *= (1.f/32.f);
        float v = 0.f;
        for (int g = 0; g < 32; g++){ float d = sh2[tid*33 + g] - m; v += d*d; }
        v *= (1.f/32.f);
        smean[tid] = m; srstd[tid] = rsqrtf(v + 1e-5f);
    }
    __syncthreads();
    for (int idx = tid; idx < 2048; idx += 256){
        int i = idx >> 5, g = idx & 31;
        float val = (sh2[i*33 + g] - smean[i]) * srstd[i] * slg[g] + slb[g];
        size_t o = (((size_t)b*64 + i)*256 + t)*32 + g;
        __nv_bfloat16 hi = __float2bfloat16(val);
        g_hencH[o] = hi;
        g_hencL[o] = __float2bfloat16(val - __bfloat162float(hi));
    }
}

// ---- mma GEMM: xg0 = henc @ Wih0^T (M=1M, N=384 both dirs, K=32), 3-term ----
__global__ __launch_bounds__(256,2) void k_xproj0(){
    __shared__ uint32_t sA[2][16*20];
    int tid = threadIdx.x;
    int w = tid >> 5, lane = tid & 31;
    int g = lane >> 2, tig = lane & 3;
    size_t Rbase = (size_t)blockIdx.x * 1024;

    uint32_t bh[6][2][2];
    #pragma unroll
    for (int nt = 0; nt < 6; nt++){
        int n = w*48 + nt*8 + g;
        const uint32_t* wp = (const uint32_t*)g_W0hi + n*16;
        #pragma unroll
        for (int ks = 0; ks < 2; ks++){
            bh[nt][ks][0] = wp[ks*8 + tig];
            bh[nt][ks][1] = wp[ks*8 + 4 + tig];
        }
    }
    const uint32_t* blo = (const uint32_t*)g_W0lo;
    const uint32_t* hH = (const uint32_t*)g_hencH;
    const uint32_t* hL = (const uint32_t*)g_hencL;

    for (int mt = 0; mt < 64; mt++){
        size_t R = Rbase + mt*16;
        __syncthreads();
        for (int i = tid; i < 256; i += 256){
            int row = i >> 4, c = i & 15;
            sA[0][row*20 + c] = hH[(R+row)*16 + c];
            sA[1][row*20 + c] = hL[(R+row)*16 + c];
        }
        __syncthreads();
        float acc[6][4];
        #pragma unroll
        for (int nt=0;nt<6;nt++){ acc[nt][0]=0.f; acc[nt][1]=0.f; acc[nt][2]=0.f; acc[nt][3]=0.f; }
        #pragma unroll
        for (int term = 0; term < 3; term++){
            const uint32_t* As = sA[term == 1 ? 1 : 0];
            #pragma unroll
            for (int ks = 0; ks < 2; ks++){
                uint32_t a0 = As[g*20 + ks*8 + tig];
                uint32_t a1 = As[(g+8)*20 + ks*8 + tig];
                uint32_t a2 = As[g*20 + ks*8 + 4 + tig];
                uint32_t a3 = As[(g+8)*20 + ks*8 + 4 + tig];
                #pragma unroll
                for (int nt = 0; nt < 6; nt++){
                    uint32_t b0, b1;
                    if (term < 2){ b0 = bh[nt][ks][0]; b1 = bh[nt][ks][1]; }
                    else {
                        int n = w*48 + nt*8 + g;
                        b0 = __ldg(blo + n*16 + ks*8 + tig);
                        b1 = __ldg(blo + n*16 + ks*8 + 4 + tig);
                    }
                    asm volatile(
                        "mma.sync.aligned.m16n8k16.row.col.f32.bf16.bf16.f32 "
                        "{%0,%1,%2,%3}, {%4,%5,%6,%7}, {%8,%9}, {%0,%1,%2,%3};"
                        : "+f"(acc[nt][0]), "+f"(acc[nt][1]), "+f"(acc[nt][2]), "+f"(acc[nt][3])
                        : "r"(a0), "r"(a1), "r"(a2), "r"(a3), "r"(b0), "r"(b1));
                }
            }
        }
        #pragma unroll
        for (int nt = 0; nt < 6; nt++){
            int col = w*48 + nt*8 + tig*2;
            int dir = col >= 192;
            int lc = col - dir*192;
            float* base = g_xg0 + (size_t)dir*201326592;
            *(float2*)(base + (R+g)*192 + lc)   = make_float2(acc[nt][0], acc[nt][1]);
            *(float2*)(base + (R+g+8)*192 + lc) = make_float2(acc[nt][2], acc[nt][3]);
        }
    }
}

// ---- BiGRU layer 0: hidden recurrence only, 8 seqs per CTA ----
__global__ __launch_bounds__(192,2) void k_gru0h(
    const float* __restrict__ Whh, const float* __restrict__ bih, const float* __restrict__ bhh)
{
    int n0 = blockIdx.x * 8, dir = blockIdx.y;
    int g = threadIdx.x;
    __shared__ __align__(16) float sh[8][64];
    __shared__ float sgi[8][192], sgh[8][192];

    ull wh[32];
    const ull* p = (const ull*)(Whh + ((size_t)dir*192 + g)*64);
    #pragma unroll
    for (int k = 0; k < 32; k++) wh[k] = p[k];
    float bi = bih[dir*192 + g], bh = bhh[dir*192 + g];

    for (int u = g; u < 512; u += 192) sh[u>>6][u&63] = 0.f;
    __syncthreads();

    const float* xgb = g_xg0 + (size_t)dir*201326592;
    int t0 = dir ? 255 : 0;
    float xr[8];
    #pragma unroll
    for (int q = 0; q < 8; q++) xr[q] = xgb[((size_t)(n0+q)*256 + t0)*192 + g];

    for (int s = 0; s < 256; s++){
        int t = dir ? 255 - s : s;
        #pragma unroll
        for (int q = 0; q < 8; q++) sgi[q][g] = xr[q] + bi;
        if (s < 255){
            int tn = dir ? 254 - s : s + 1;
            #pragma unroll
            for (int q = 0; q < 8; q++) xr[q] = xgb[((size_t)(n0+q)*256 + tn)*192 + g];
        }
        #pragma unroll
        for (int q = 0; q < 8; q++){
            const ulonglong2* h4 = (const ulonglong2*)sh[q];
            ull b0 = 0, b1 = 0;
            #pragma unroll
            for (int k = 0; k < 16; k++){ ulonglong2 v = h4[k]; fma2(b0, wh[2*k], v.x); fma2(b1, wh[2*k+1], v.y); }
            sgh[q][g] = hsum2(b0) + hsum2(b1) + bh;
        }
        __syncthreads();
        for (int u = g; u < 512; u += 192){
            int q = u >> 6, hh = u & 63;
            float r  = sigf(sgi[q][hh] + sgh[q][hh]);
            float z  = sigf(sgi[q][64+hh] + sgh[q][64+hh]);
            float nn = tanhf(sgi[q][128+hh] + r*sgh[q][128+hh]);
            float h  = (1.f - z)*nn + z*sh[q][hh];
            sh[q][hh] = h;
            __nv_bfloat16 hi = __float2bfloat16(h);
            __nv_bfloat16 lo = __float2bfloat16(h - __bfloat162float(hi));
            size_t idx = ((size_t)(n0+q)*256 + t)*128 + dir*64 + hh;
            g_h0H[idx] = hi; g_h0L[idx] = lo;
        }
        __syncthreads();
    }
}

// ---- mma GEMM: xg1 = h0 @ Wih1^T (M=1M, N=192, K=128), 3-term ----
__global__ __launch_bounds__(256,2) void k_xproj1(){
    __shared__ uint32_t sA[2][16*68];
    int tid = threadIdx.x;
    int w = tid >> 5, lane = tid & 31;
    int g = lane >> 2, tig = lane & 3;
    size_t Rbase = (size_t)blockIdx.x * 1024;

    uint32_t bh[3][8][2];
    #pragma unroll
    for (int nt = 0; nt < 3; nt++){
        int n = w*24 + nt*8 + g;
        const uint32_t* wp = (const uint32_t*)g_W1hi + n*64;
        #pragma unroll
        for (int ks = 0; ks < 8; ks++){
            bh[nt][ks][0] = wp[ks*8 + tig];
            bh[nt][ks][1] = wp[ks*8 + 4 + tig];
        }
    }
    const uint32_t* blo = (const uint32_t*)g_W1lo;
    const uint32_t* h0Hu = (const uint32_t*)g_h0H;
    const uint32_t* h0Lu = (const uint32_t*)g_h0L;

    for (int mt = 0; mt < 64; mt++){
        size_t R = Rbase + mt*16;
        __syncthreads();
        for (int i = tid; i < 1024; i += 256){
            int row = i >> 6, c = i & 63;
            sA[0][row*68 + c] = h0Hu[(R+row)*64 + c];
            sA[1][row*68 + c] = h0Lu[(R+row)*64 + c];
        }
        __syncthreads();
        float acc[3][4];
        #pragma unroll
        for (int nt=0;nt<3;nt++){ acc[nt][0]=0.f; acc[nt][1]=0.f; acc[nt][2]=0.f; acc[nt][3]=0.f; }
        #pragma unroll
        for (int term = 0; term < 3; term++){
            const uint32_t* As = sA[term == 1 ? 1 : 0];
            #pragma unroll
            for (int ks = 0; ks < 8; ks++){
                uint32_t a0 = As[g*68 + ks*8 + tig];
                uint32_t a1 = As[(g+8)*68 + ks*8 + tig];
                uint32_t a2 = As[g*68 + ks*8 + 4 + tig];
                uint32_t a3 = As[(g+8)*68 + ks*8 + 4 + tig];
                #pragma unroll
                for (int nt = 0; nt < 3; nt++){
                    uint32_t b0, b1;
                    if (term < 2){ b0 = bh[nt][ks][0]; b1 = bh[nt][ks][1]; }
                    else {
                        int n = w*24 + nt*8 + g;
                        b0 = __ldg(blo + n*64 + ks*8 + tig);
                        b1 = __ldg(blo + n*64 + ks*8 + 4 + tig);
                    }
                    asm volatile(
                        "mma.sync.aligned.m16n8k16.row.col.f32.bf16.bf16.f32 "
                        "{%0,%1,%2,%3}, {%4,%5,%6,%7}, {%8,%9}, {%0,%1,%2,%3};"
                        : "+f"(acc[nt][0]), "+f"(acc[nt][1]), "+f"(acc[nt][2]), "+f"(acc[nt][3])
                        : "r"(a0), "r"(a1), "r"(a2), "r"(a3), "r"(b0), "r"(b1));
                }
            }
        }
        #pragma unroll
        for (int nt = 0; nt < 3; nt++){
            int col = w*24 + nt*8 + tig*2;
            *(float2*)(g_xg1 + (R+g)*192 + col)   = make_float2(acc[nt][0], acc[nt][1]);
            *(float2*)(g_xg1 + (R+g+8)*192 + col) = make_float2(acc[nt][2], acc[nt][3]);
        }
    }
}

// ---- GRU layer 1 fwd, hidden recurrence only, 8 seqs per CTA ----
__global__ __launch_bounds__(192,2) void k_gru1h(
    const float* __restrict__ Whh, const float* __restrict__ bih, const float* __restrict__ bhh)
{
    int n0 = blockIdx.x * 8;
    int g = threadIdx.x;
    __shared__ __align__(16) float sh[8][64];
    __shared__ float sgi[8][192], sgh[8][192];

    ull wh[32];
    const ull* p = (const ull*)(Whh + (size_t)g*64);
    #pragma unroll
    for (int k = 0; k < 32; k++) wh[k] = p[k];
    float bi = bih[g], bh = bhh[g];

    for (int u = g; u < 512; u += 192) sh[u>>6][u&63] = 0.f;
    __syncthreads();

    float xr[8];
    #pragma unroll
    for (int q = 0; q < 8; q++) xr[q] = g_xg1[((size_t)(n0+q)*256)*192 + g];

    for (int t = 0; t < 256; t++){
        #pragma unroll
        for (int q = 0; q < 8; q++) sgi[q][g] = xr[q] + bi;
        if (t < 255){
            #pragma unroll
            for (int q = 0; q < 8; q++) xr[q] = g_xg1[((size_t)(n0+q)*256 + t + 1)*192 + g];
        }
        #pragma unroll
        for (int q = 0; q < 8; q++){
            const ulonglong2* h4 = (const ulonglong2*)sh[q];
            ull b0 = 0, b1 = 0;
            #pragma unroll
            for (int k = 0; k < 16; k++){ ulonglong2 v = h4[k]; fma2(b0, wh[2*k], v.x); fma2(b1, wh[2*k+1], v.y); }
            sgh[q][g] = hsum2(b0) + hsum2(b1) + bh;
        }
        __syncthreads();
        for (int u = g; u < 512; u += 192){
            int q = u >> 6, hh = u & 63;
            float r  = sigf(sgi[q][hh] + sgh[q][hh]);
            float z  = sigf(sgi[q][64+hh] + sgh[q][64+hh]);
            float nn = tanhf(sgi[q][128+hh] + r*sgh[q][128+hh]);
            float h  = (1.f - z)*nn + z*sh[q][hh];
            sh[q][hh] = h;
            if (t == 255) g_last[(n0+q)*128 + hh] = h;
        }
        __syncthreads();
    }
}

__global__ __launch_bounds__(192,2) void k_gru1b(
    const float* __restrict__ Wih, const float* __restrict__ Whh,
    const float* __restrict__ bih, const float* __restrict__ bhh)
{
    int tid = threadIdx.x;
    __shared__ __align__(16) float sx[128];
    __shared__ float sgi[192];
    ull w[64];
    const ull* p = (const ull*)(Wih + 192UL*128 + (size_t)tid*128);
    #pragma unroll
    for (int k = 0; k < 64; k++) w[k] = p[k];
    float bias = bih[192 + tid];

    for (int it = 0; it < 64; it++){
        int n = blockIdx.x*64 + it;
        if (tid < 128){
            size_t idx = ((size_t)n*256 + 255)*128 + tid;
            sx[tid] = __bfloat162float(g_h0H[idx]) + __bfloat162float(g_h0L[idx]);
        }
        __syncthreads();
        ull a0 = 0, a1 = 0;
        const ulonglong2* v4 = (const ulonglong2*)sx;
        #pragma unroll
        for (int k = 0; k < 32; k++){ ulonglong2 v = v4[k]; fma2(a0, w[2*k], v.x); fma2(a1, w[2*k+1], v.y); }
        sgi[tid] = hsum2(a0) + hsum2(a1) + bias;
        __syncthreads();
        if (tid < 64){
            float r  = sigf(sgi[tid]      + bhh[192 + tid]);
            float z  = sigf(sgi[64 + tid] + bhh[192 + 64 + tid]);
            float nn = tanhf(sgi[128+tid] + r * bhh[192 + 128 + tid]);
            g_last[n*128 + 64 + tid] = (1.f - z)*nn;
        }
    }
}

__global__ __launch_bounds__(128) void k_head(
    const float* __restrict__ pool_W, const float* __restrict__ pool_b,
    const float* __restrict__ mu_W, const float* __restrict__ mu_b,
    const float* __restrict__ logv_W, const float* __restrict__ logv_b,
    const float* __restrict__ dec_W, const float* __restrict__ dec_b,
    const float* __restrict__ lstm_Wih, const float* __restrict__ lstm_bih,
    const float* __restrict__ lstm_bhh,
    float* __restrict__ out)
{
    int b = blockIdx.x, tid = threadIdx.x;
    __shared__ float slast[128], shp[32], smu[32], sdh[64];
    float s = 0.f;
    for (int c = 0; c < 64; c++) s += g_last[(b*64 + c)*128 + tid];
    slast[tid] = s * (1.f/64.f);
    __syncthreads();
    if (tid < 32){
        float acc = pool_b[tid];
        for (int k = 0; k < 128; k++) acc += pool_W[tid*128 + k] * slast[k];
        shp[tid] = fmaxf(acc, 0.f);
    }
    __syncthreads();
    if (tid < 32){
        float acc = mu_b[tid];
        for (int k = 0; k < 32; k++) acc += mu_W[tid*32 + k] * shp[k];
        smu[tid] = acc;
        out[64UL*256*64 + b*32 + tid] = acc;
    } else if (tid < 64){
        int j = tid - 32;
        float acc = logv_b[j];
        for (int k = 0; k < 32; k++) acc += logv_W[j*32 + k] * shp[k];
        out[64UL*256*64 + 2048 + b*32 + j] = acc;
    }
    __syncthreads();
    if (tid < 64){
        float acc = dec_b[tid];
        for (int k = 0; k < 32; k++) acc += dec_W[tid*32 + k] * smu[k];
        sdh[tid] = fmaxf(acc, 0.f);
    }
    __syncthreads();
    for (int gate = tid; gate < 256; gate += 128){
        float acc = lstm_bih[gate] + lstm_bhh[gate];
        for (int k = 0; k < 64; k++) acc += lstm_Wih[gate*64 + k] * sdh[k];
        g_dxg[b*256 + gate] = acc;
    }
}

__global__ __launch_bounds__(256,1) void k_lstm1(const float* __restrict__ Whh)
{
    int b = blockIdx.x, tid = threadIdx.x;
    __shared__ __align__(16) float sh[64];
    __shared__ float sg[256];
    ull w[32];
    const ull* p = (const ull*)(Whh + (size_t)tid*64);
    #pragma unroll
    for (int k = 0; k < 32; k++) w[k] = p[k];
    float dxg = g_dxg[b*256 + tid];
    if (tid < 64) sh[tid] = 0.f;
    float c = 0.f;
    for (int t = 0; t < 256; t++){
        __syncthreads();
        ull a0 = 0, a1 = 0;
        const ulonglong2* v4 = (const ulonglong2*)sh;
        #pragma unroll
        for (int k = 0; k < 16; k++){ ulonglong2 v = v4[k]; fma2(a0, w[2*k], v.x); fma2(a1, w[2*k+1], v.y); }
        sg[tid] = hsum2(a0) + hsum2(a1) + dxg;
        __syncthreads();
        if (tid < 64){
            float i_ = sigf(sg[tid]), f_ = sigf(sg[64+tid]);
            float gg = tanhf(sg[128+tid]), o_ = sigf(sg[192+tid]);
            c = f_*c + i_*gg;
            float h = o_*tanhf(c);
            sh[tid] = h;
            g_h1d[((size_t)b*256 + t)*64 + tid] = h;
        }
    }
}

__global__ __launch_bounds__(256,1) void k_lstm2(
    const float* __restrict__ Wih, const float* __restrict__ Whh,
    const float* __restrict__ bih, const float* __restrict__ bhh,
    const float* __restrict__ out_W, const float* __restrict__ out_b,
    float* __restrict__ out)
{
    int b = blockIdx.x, tid = threadIdx.x;
    __shared__ __align__(16) float sx[64];
    __shared__ __align__(16) float sh[64];
    __shared__ float sg[256];
    __shared__ float soW[64*64];
    for (int i = tid; i < 4096; i += 256){ int c = i >> 6, k = i & 63; soW[k*64 + c] = out_W[i]; }
    ull wi[32], wh[32];
    const ull* p = (const ull*)(Wih + 256UL*64 + (size_t)tid*64);
    const ull* q = (const ull*)(Whh + 256UL*64 + (size_t)tid*64);
    #pragma unroll
    for (int k = 0; k < 32; k++){ wi[k] = p[k]; wh[k] = q[k]; }
    float bias = bih[256 + tid] + bhh[256 + tid];
    if (tid < 64) sh[tid] = 0.f;
    float c = 0.f;
    float ob = (tid >= 64 && tid < 128) ? out_b[tid - 64] : 0.f;
    const float* xb = g_h1d + (size_t)b*256*64;
    for (int t = 0; t < 256; t++){
        if (tid < 64) sx[tid] = xb[t*64 + tid];
        __syncthreads();
        ull a0 = 0, a1 = 0;
        const ulonglong2* x4 = (const ulonglong2*)sx;
        const ulonglong2* h4 = (const ulonglong2*)sh;
        #pragma unroll
        for (int k = 0; k < 16; k++){ ulonglong2 v = x4[k]; fma2(a0, wi[2*k], v.x); fma2(a1, wi[2*k+1], v.y); }
        #pragma unroll
        for (int k = 0; k < 16; k++){ ulonglong2 v = h4[k]; fma2(a0, wh[2*k], v.x); fma2(a1, wh[2*k+1], v.y); }
        sg[tid] = hsum2(a0) + hsum2(a1) + bias;
        __syncthreads();
        if (tid < 64){
            float i_ = sigf(sg[tid]), f_ = sigf(sg[64+tid]);
            float gg = tanhf(sg[128+tid]), o_ = sigf(sg[192+tid]);
            c = f_*c + i_*gg;
            sh[tid] = o_*tanhf(c);
        }
        __syncthreads();
        if (tid >= 64 && tid < 128){
            int cc = tid - 64;
            float acc = ob;
            #pragma unroll 8
            for (int k = 0; k < 64; k++) acc += soW[k*64 + cc] * sh[k];
            out[((size_t)b*256 + t)*64 + cc] = acc;
        }
    }
}

extern "C" void kernel_launch(void* const* d_in, const int* in_sizes, int n_in,
                              void* d_out, int out_size)
{
    const float* x      = (const float*)d_in[0];
    const float* adj1   = (const float*)d_in[1];
    const float* W1     = (const float*)d_in[2];
    const float* b1     = (const float*)d_in[3];
    const float* adj2   = (const float*)d_in[4];
    const float* W2     = (const float*)d_in[5];
    const float* b2     = (const float*)d_in[6];
    const float* ln_g   = (const float*)d_in[7];
    const float* ln_b   = (const float*)d_in[8];
    const float* g0Wih  = (const float*)d_in[9];
    const float* g0Whh  = (const float*)d_in[10];
    const float* g0bih  = (const float*)d_in[11];
    const float* g0bhh  = (const float*)d_in[12];
    const float* g1Wih  = (const float*)d_in[13];
    const float* g1Whh  = (const float*)d_in[14];
    const float* g1bih  = (const float*)d_in[15];
    const float* g1bhh  = (const float*)d_in[16];
    const float* pool_W = (const float*)d_in[17];
    const float* pool_b = (const float*)d_in[18];
    const float* mu_W   = (const float*)d_in[19];
    const float* mu_b   = (const float*)d_in[20];
    const float* logv_W = (const float*)d_in[21];
    const float* logv_b = (const float*)d_in[22];
    const float* dec_W  = (const float*)d_in[23];
    const float* dec_b  = (const float*)d_in[24];
    const float* lWih   = (const float*)d_in[25];
    const float* lWhh   = (const float*)d_in[26];
    const float* lbih   = (const float*)d_in[27];
    const float* lbhh   = (const float*)d_in[28];
    const float* out_W  = (const float*)d_in[29];
    const float* out_b  = (const float*)d_in[30];
    float* out = (float*)d_out;

    k_softmax<<<1, 64>>>(adj1, adj2);
    k_prepW<<<1, 256>>>(g1Wih, g0Wih);
    k_gnn<<<16384, 256>>>(x, W1, b1, W2, b2, ln_g, ln_b);
    k_xproj0<<<1024, 256>>>();
    k_gru0h<<<dim3(512, 2), 192>>>(g0Whh, g0bih, g0bhh);
    k_xproj1<<<1024, 256>>>();
    k_gru1h<<<512, 192>>>(g1Whh, g1bih, g1bhh);
    k_gru1b<<<64, 192>>>(g1Wih, g1Whh, g1bih, g1bhh);
    k_head<<<64, 128>>>(pool_W, pool_b, mu_W, mu_b, logv_W, logv_b,
                        dec_W, dec_b, lWih, lbih, lbhh, out);
    k_lstm1<<<64, 256>>>(lWhh);
    k_lstm2<<<64, 256>>>(lWih, lWhh, lbih, lbhh, out_W, out_b, out);
}

// round 9
// speedup vs baseline: 1.5643x; 1.0874x over previous
#include <cuda_runtime.h>
#include <cuda_bf16.h>
#include <cstdint>
#include <math.h>

typedef unsigned long long ull;

__device__ float g_A1[64*64];
__device__ float g_A2[64*64];
__device__ __nv_bfloat16 g_hencH[4096UL*256*32];
__device__ __nv_bfloat16 g_hencL[4096UL*256*32];
__device__ __nv_bfloat16 g_h0H[4096UL*256*128];
__device__ __nv_bfloat16 g_h0L[4096UL*256*128];
__device__ __nv_bfloat16 g_W1hi[192*128];
__device__ __nv_bfloat16 g_W1lo[192*128];
__device__ __nv_bfloat16 g_W0hi[384*32];
__device__ __nv_bfloat16 g_W0lo[384*32];
__device__ float g_xg0[2UL*4096*256*192];
__device__ float g_xg1[4096UL*256*192];
__device__ float g_last[4096*128];
__device__ float g_dxg[64*256];
__device__ float g_h1d[64UL*256*64];

__device__ __forceinline__ void fma2(ull &acc, ull a, ull b){
    asm("fma.rn.f32x2 %0, %1, %2, %0;" : "+l"(acc) : "l"(a), "l"(b));
}
__device__ __forceinline__ float hsum2(ull a){
    float lo, hi; asm("mov.b64 {%0,%1}, %2;" : "=f"(lo), "=f"(hi) : "l"(a));
    return lo + hi;
}
// fast sigmoid/tanh: MUFU.EX2 + MUFU.RCP based; abs err ~2e-7, correct saturation
__device__ __forceinline__ float sigf(float x){
    return __fdividef(1.f, 1.f + __expf(-x));
}
__device__ __forceinline__ float tanf_(float x){
    return __fmaf_rn(2.f, __fdividef(1.f, 1.f + __expf(-2.f*x)), -1.f);
}

__global__ void k_softmax(const float* __restrict__ adj1, const float* __restrict__ adj2){
    int i = threadIdx.x;
    for (int w = 0; w < 2; w++){
        const float* a = w ? adj2 : adj1;
        float* o = w ? g_A2 : g_A1;
        float mx = -1e30f;
        for (int j = 0; j < 64; j++) mx = fmaxf(mx, a[i*64+j]);
        float s = 0.f;
        for (int j = 0; j < 64; j++) s += expf(a[i*64+j] - mx);
        float inv = 1.f / s;
        for (int j = 0; j < 64; j++) o[i*64+j] = expf(a[i*64+j] - mx) * inv;
    }
}

__global__ void k_prepW(const float* __restrict__ W1, const float* __restrict__ W0){
    for (int i = threadIdx.x; i < 24576; i += 256){
        float v = W1[i];
        __nv_bfloat16 hi = __float2bfloat16(v);
        g_W1hi[i] = hi; g_W1lo[i] = __float2bfloat16(v - __bfloat162float(hi));
    }
    for (int i = threadIdx.x; i < 12288; i += 256){
        float v = W0[i];
        __nv_bfloat16 hi = __float2bfloat16(v);
        g_W0hi[i] = hi; g_W0lo[i] = __float2bfloat16(v - __bfloat162float(hi));
    }
}

__global__ __launch_bounds__(256) void k_gnn(
    const float* __restrict__ x,
    const float* __restrict__ W1, const float* __restrict__ b1,
    const float* __restrict__ W2, const float* __restrict__ b2,
    const float* __restrict__ lng, const float* __restrict__ lnb)
{
    int bt = blockIdx.x;
    int b = bt >> 8, t = bt & 255;
    int tid = threadIdx.x;

    __shared__ float sA2[64*65];
    __shared__ float sW2t[1024];
    __shared__ __align__(16) float sx[64];
    __shared__ float s1[64];
    __shared__ __align__(16) float sh1[2048];
    __shared__ __align__(16) float sagg[2048];
    __shared__ float sh2[64*33];
    __shared__ float sW1[32], sb1[32], sb2[32], slg[32], slb[32];
    __shared__ float smean[64], srstd[64];

    for (int i = tid; i < 4096; i += 256) sA2[(i>>6)*65 + (i&63)] = g_A2[i];
    for (int i = tid; i < 1024; i += 256){ int gp = i>>5, k = i&31; sW2t[k*32+gp] = W2[i]; }
    if (tid < 64) sx[tid] = x[(size_t)bt*64 + tid];
    if (tid < 32){ sW1[tid]=W1[tid]; sb1[tid]=b1[tid]; sb2[tid]=b2[tid]; slg[tid]=lng[tid]; slb[tid]=lnb[tid]; }
    __syncthreads();

    if (tid < 64){
        float s = 0.f; const float* a = g_A1 + tid*64;
        #pragma unroll 8
        for (int j = 0; j < 64; j++) s += a[j]*sx[j];
        s1[tid] = s;
    }
    __syncthreads();
    for (int i = tid; i < 2048; i += 256){ int j = i>>5, g = i&31; sh1[i] = fmaxf(sW1[g]*s1[j] + sb1[g], 0.f); }
    __syncthreads();
    {
        int i = tid >> 2, g0 = (tid & 3) * 8;
        float4 a0 = {0,0,0,0}, a1 = {0,0,0,0};
        #pragma unroll 4
        for (int j = 0; j < 64; j++){
            float a = sA2[i*65 + j];
            float4 h0 = *(const float4*)(sh1 + j*32 + g0);
            float4 h1 = *(const float4*)(sh1 + j*32 + g0 + 4);
            a0.x += a*h0.x; a0.y += a*h0.y; a0.z += a*h0.z; a0.w += a*h0.w;
            a1.x += a*h1.x; a1.y += a*h1.y; a1.z += a*h1.z; a1.w += a*h1.w;
        }
        *(float4*)(sagg + i*32 + g0)     = a0;
        *(float4*)(sagg + i*32 + g0 + 4) = a1;
    }
    __syncthreads();
    #pragma unroll
    for (int q = 0; q < 8; q++){
        int idx = tid + (q << 8);
        int i = idx >> 5, gp = idx & 31;
        float acc = sb2[gp];
        #pragma unroll 8
        for (int k = 0; k < 32; k++) acc += sagg[i*32 + k] * sW2t[k*32 + gp];
        sh2[i*33 + gp] = fmaxf(acc, 0.f);
    }
    __syncthreads();
    if (tid < 64){
        float m = 0.f;
        for (int g = 0; g < 32; g++) m += sh2[tid*33 + g];
        m *= (1.f/32.f);
        float v = 0.f;
        for (int g = 0; g < 32; g++){ float d = sh2[tid*33 + g] - m; v += d*d; }
        v *= (1.f/32.f);
        smean[tid] = m; srstd[tid] = rsqrtf(v + 1e-5f);
    }
    __syncthreads();
    for (int idx = tid; idx < 2048; idx += 256){
        int i = idx >> 5, g = idx & 31;
        float val = (sh2[i*33 + g] - smean[i]) * srstd[i] * slg[g] + slb[g];
        size_t o = (((size_t)b*64 + i)*256 + t)*32 + g;
        __nv_bfloat16 hi = __float2bfloat16(val);
        g_hencH[o] = hi;
        g_hencL[o] = __float2bfloat16(val - __bfloat162float(hi));
    }
}

// ---- mma GEMM: xg0 = henc @ Wih0^T (M=1M, N=384 both dirs, K=32), 3-term ----
__global__ __launch_bounds__(256,2) void k_xproj0(){
    __shared__ uint32_t sA[2][16*20];
    int tid = threadIdx.x;
    int w = tid >> 5, lane = tid & 31;
    int g = lane >> 2, tig = lane & 3;
    size_t Rbase = (size_t)blockIdx.x * 1024;

    uint32_t bh[6][2][2];
    #pragma unroll
    for (int nt = 0; nt < 6; nt++){
        int n = w*48 + nt*8 + g;
        const uint32_t* wp = (const uint32_t*)g_W0hi + n*16;
        #pragma unroll
        for (int ks = 0; ks < 2; ks++){
            bh[nt][ks][0] = wp[ks*8 + tig];
            bh[nt][ks][1] = wp[ks*8 + 4 + tig];
        }
    }
    const uint32_t* blo = (const uint32_t*)g_W0lo;
    const uint32_t* hH = (const uint32_t*)g_hencH;
    const uint32_t* hL = (const uint32_t*)g_hencL;

    for (int mt = 0; mt < 64; mt++){
        size_t R = Rbase + mt*16;
        __syncthreads();
        for (int i = tid; i < 256; i += 256){
            int row = i >> 4, c = i & 15;
            sA[0][row*20 + c] = hH[(R+row)*16 + c];
            sA[1][row*20 + c] = hL[(R+row)*16 + c];
        }
        __syncthreads();
        float acc[6][4];
        #pragma unroll
        for (int nt=0;nt<6;nt++){ acc[nt][0]=0.f; acc[nt][1]=0.f; acc[nt][2]=0.f; acc[nt][3]=0.f; }
        #pragma unroll
        for (int term = 0; term < 3; term++){
            const uint32_t* As = sA[term == 1 ? 1 : 0];
            #pragma unroll
            for (int ks = 0; ks < 2; ks++){
                uint32_t a0 = As[g*20 + ks*8 + tig];
                uint32_t a1 = As[(g+8)*20 + ks*8 + tig];
                uint32_t a2 = As[g*20 + ks*8 + 4 + tig];
                uint32_t a3 = As[(g+8)*20 + ks*8 + 4 + tig];
                #pragma unroll
                for (int nt = 0; nt < 6; nt++){
                    uint32_t b0, b1;
                    if (term < 2){ b0 = bh[nt][ks][0]; b1 = bh[nt][ks][1]; }
                    else {
                        int n = w*48 + nt*8 + g;
                        b0 = __ldg(blo + n*16 + ks*8 + tig);
                        b1 = __ldg(blo + n*16 + ks*8 + 4 + tig);
                    }
                    asm volatile(
                        "mma.sync.aligned.m16n8k16.row.col.f32.bf16.bf16.f32 "
                        "{%0,%1,%2,%3}, {%4,%5,%6,%7}, {%8,%9}, {%0,%1,%2,%3};"
                        : "+f"(acc[nt][0]), "+f"(acc[nt][1]), "+f"(acc[nt][2]), "+f"(acc[nt][3])
                        : "r"(a0), "r"(a1), "r"(a2), "r"(a3), "r"(b0), "r"(b1));
                }
            }
        }
        #pragma unroll
        for (int nt = 0; nt < 6; nt++){
            int col = w*48 + nt*8 + tig*2;
            int dir = col >= 192;
            int lc = col - dir*192;
            float* base = g_xg0 + (size_t)dir*201326592;
            *(float2*)(base + (R+g)*192 + lc)   = make_float2(acc[nt][0], acc[nt][1]);
            *(float2*)(base + (R+g+8)*192 + lc) = make_float2(acc[nt][2], acc[nt][3]);
        }
    }
}

// ---- BiGRU layer 0: hidden recurrence only, 8 seqs per CTA ----
__global__ __launch_bounds__(192,2) void k_gru0h(
    const float* __restrict__ Whh, const float* __restrict__ bih, const float* __restrict__ bhh)
{
    int n0 = blockIdx.x * 8, dir = blockIdx.y;
    int g = threadIdx.x;
    __shared__ __align__(16) float sh[8][64];
    __shared__ float sgi[8][192], sgh[8][192];

    ull wh[32];
    const ull* p = (const ull*)(Whh + ((size_t)dir*192 + g)*64);
    #pragma unroll
    for (int k = 0; k < 32; k++) wh[k] = p[k];
    float bi = bih[dir*192 + g], bh = bhh[dir*192 + g];

    for (int u = g; u < 512; u += 192) sh[u>>6][u&63] = 0.f;
    __syncthreads();

    const float* xgb = g_xg0 + (size_t)dir*201326592;
    int t0 = dir ? 255 : 0;
    float xr[8];
    #pragma unroll
    for (int q = 0; q < 8; q++) xr[q] = xgb[((size_t)(n0+q)*256 + t0)*192 + g];

    for (int s = 0; s < 256; s++){
        int t = dir ? 255 - s : s;
        #pragma unroll
        for (int q = 0; q < 8; q++) sgi[q][g] = xr[q] + bi;
        if (s < 255){
            int tn = dir ? 254 - s : s + 1;
            #pragma unroll
            for (int q = 0; q < 8; q++) xr[q] = xgb[((size_t)(n0+q)*256 + tn)*192 + g];
        }
        #pragma unroll
        for (int q = 0; q < 8; q++){
            const ulonglong2* h4 = (const ulonglong2*)sh[q];
            ull b0 = 0, b1 = 0;
            #pragma unroll
            for (int k = 0; k < 16; k++){ ulonglong2 v = h4[k]; fma2(b0, wh[2*k], v.x); fma2(b1, wh[2*k+1], v.y); }
            sgh[q][g] = hsum2(b0) + hsum2(b1) + bh;
        }
        __syncthreads();
        for (int u = g; u < 512; u += 192){
            int q = u >> 6, hh = u & 63;
            float r  = sigf(sgi[q][hh] + sgh[q][hh]);
            float z  = sigf(sgi[q][64+hh] + sgh[q][64+hh]);
            float nn = tanf_(sgi[q][128+hh] + r*sgh[q][128+hh]);
            float h  = (1.f - z)*nn + z*sh[q][hh];
            sh[q][hh] = h;
            __nv_bfloat16 hi = __float2bfloat16(h);
            __nv_bfloat16 lo = __float2bfloat16(h - __bfloat162float(hi));
            size_t idx = ((size_t)(n0+q)*256 + t)*128 + dir*64 + hh;
            g_h0H[idx] = hi; g_h0L[idx] = lo;
        }
        __syncthreads();
    }
}

// ---- mma GEMM: xg1 = h0 @ Wih1^T (M=1M, N=192, K=128), 3-term ----
__global__ __launch_bounds__(256,2) void k_xproj1(){
    __shared__ uint32_t sA[2][16*68];
    int tid = threadIdx.x;
    int w = tid >> 5, lane = tid & 31;
    int g = lane >> 2, tig = lane & 3;
    size_t Rbase = (size_t)blockIdx.x * 1024;

    uint32_t bh[3][8][2];
    #pragma unroll
    for (int nt = 0; nt < 3; nt++){
        int n = w*24 + nt*8 + g;
        const uint32_t* wp = (const uint32_t*)g_W1hi + n*64;
        #pragma unroll
        for (int ks = 0; ks < 8; ks++){
            bh[nt][ks][0] = wp[ks*8 + tig];
            bh[nt][ks][1] = wp[ks*8 + 4 + tig];
        }
    }
    const uint32_t* blo = (const uint32_t*)g_W1lo;
    const uint32_t* h0Hu = (const uint32_t*)g_h0H;
    const uint32_t* h0Lu = (const uint32_t*)g_h0L;

    for (int mt = 0; mt < 64; mt++){
        size_t R = Rbase + mt*16;
        __syncthreads();
        for (int i = tid; i < 1024; i += 256){
            int row = i >> 6, c = i & 63;
            sA[0][row*68 + c] = h0Hu[(R+row)*64 + c];
            sA[1][row*68 + c] = h0Lu[(R+row)*64 + c];
        }
        __syncthreads();
        float acc[3][4];
        #pragma unroll
        for (int nt=0;nt<3;nt++){ acc[nt][0]=0.f; acc[nt][1]=0.f; acc[nt][2]=0.f; acc[nt][3]=0.f; }
        #pragma unroll
        for (int term = 0; term < 3; term++){
            const uint32_t* As = sA[term == 1 ? 1 : 0];
            #pragma unroll
            for (int ks = 0; ks < 8; ks++){
                uint32_t a0 = As[g*68 + ks*8 + tig];
                uint32_t a1 = As[(g+8)*68 + ks*8 + tig];
                uint32_t a2 = As[g*68 + ks*8 + 4 + tig];
                uint32_t a3 = As[(g+8)*68 + ks*8 + 4 + tig];
                #pragma unroll
                for (int nt = 0; nt < 3; nt++){
                    uint32_t b0, b1;
                    if (term < 2){ b0 = bh[nt][ks][0]; b1 = bh[nt][ks][1]; }
                    else {
                        int n = w*24 + nt*8 + g;
                        b0 = __ldg(blo + n*64 + ks*8 + tig);
                        b1 = __ldg(blo + n*64 + ks*8 + 4 + tig);
                    }
                    asm volatile(
                        "mma.sync.aligned.m16n8k16.row.col.f32.bf16.bf16.f32 "
                        "{%0,%1,%2,%3}, {%4,%5,%6,%7}, {%8,%9}, {%0,%1,%2,%3};"
                        : "+f"(acc[nt][0]), "+f"(acc[nt][1]), "+f"(acc[nt][2]), "+f"(acc[nt][3])
                        : "r"(a0), "r"(a1), "r"(a2), "r"(a3), "r"(b0), "r"(b1));
                }
            }
        }
        #pragma unroll
        for (int nt = 0; nt < 3; nt++){
            int col = w*24 + nt*8 + tig*2;
            *(float2*)(g_xg1 + (R+g)*192 + col)   = make_float2(acc[nt][0], acc[nt][1]);
            *(float2*)(g_xg1 + (R+g+8)*192 + col) = make_float2(acc[nt][2], acc[nt][3]);
        }
    }
}

// ---- GRU layer 1 fwd, hidden recurrence only, 8 seqs per CTA ----
__global__ __launch_bounds__(192,2) void k_gru1h(
    const float* __restrict__ Whh, const float* __restrict__ bih, const float* __restrict__ bhh)
{
    int n0 = blockIdx.x * 8;
    int g = threadIdx.x;
    __shared__ __align__(16) float sh[8][64];
    __shared__ float sgi[8][192], sgh[8][192];

    ull wh[32];
    const ull* p = (const ull*)(Whh + (size_t)g*64);
    #pragma unroll
    for (int k = 0; k < 32; k++) wh[k] = p[k];
    float bi = bih[g], bh = bhh[g];

    for (int u = g; u < 512; u += 192) sh[u>>6][u&63] = 0.f;
    __syncthreads();

    float xr[8];
    #pragma unroll
    for (int q = 0; q < 8; q++) xr[q] = g_xg1[((size_t)(n0+q)*256)*192 + g];

    for (int t = 0; t < 256; t++){
        #pragma unroll
        for (int q = 0; q < 8; q++) sgi[q][g] = xr[q] + bi;
        if (t < 255){
            #pragma unroll
            for (int q = 0; q < 8; q++) xr[q] = g_xg1[((size_t)(n0+q)*256 + t + 1)*192 + g];
        }
        #pragma unroll
        for (int q = 0; q < 8; q++){
            const ulonglong2* h4 = (const ulonglong2*)sh[q];
            ull b0 = 0, b1 = 0;
            #pragma unroll
            for (int k = 0; k < 16; k++){ ulonglong2 v = h4[k]; fma2(b0, wh[2*k], v.x); fma2(b1, wh[2*k+1], v.y); }
            sgh[q][g] = hsum2(b0) + hsum2(b1) + bh;
        }
        __syncthreads();
        for (int u = g; u < 512; u += 192){
            int q = u >> 6, hh = u & 63;
            float r  = sigf(sgi[q][hh] + sgh[q][hh]);
            float z  = sigf(sgi[q][64+hh] + sgh[q][64+hh]);
            float nn = tanf_(sgi[q][128+hh] + r*sgh[q][128+hh]);
            float h  = (1.f - z)*nn + z*sh[q][hh];
            sh[q][hh] = h;
            if (t == 255) g_last[(n0+q)*128 + hh] = h;
        }
        __syncthreads();
    }
}

__global__ __launch_bounds__(192,2) void k_gru1b(
    const float* __restrict__ Wih, const float* __restrict__ Whh,
    const float* __restrict__ bih, const float* __restrict__ bhh)
{
    int tid = threadIdx.x;
    __shared__ __align__(16) float sx[128];
    __shared__ float sgi[192];
    ull w[64];
    const ull* p = (const ull*)(Wih + 192UL*128 + (size_t)tid*128);
    #pragma unroll
    for (int k = 0; k < 64; k++) w[k] = p[k];
    float bias = bih[192 + tid];

    for (int it = 0; it < 64; it++){
        int n = blockIdx.x*64 + it;
        if (tid < 128){
            size_t idx = ((size_t)n*256 + 255)*128 + tid;
            sx[tid] = __bfloat162float(g_h0H[idx]) + __bfloat162float(g_h0L[idx]);
        }
        __syncthreads();
        ull a0 = 0, a1 = 0;
        const ulonglong2* v4 = (const ulonglong2*)sx;
        #pragma unroll
        for (int k = 0; k < 32; k++){ ulonglong2 v = v4[k]; fma2(a0, w[2*k], v.x); fma2(a1, w[2*k+1], v.y); }
        sgi[tid] = hsum2(a0) + hsum2(a1) + bias;
        __syncthreads();
        if (tid < 64){
            float r  = sigf(sgi[tid]      + bhh[192 + tid]);
            float z  = sigf(sgi[64 + tid] + bhh[192 + 64 + tid]);
            float nn = tanf_(sgi[128+tid] + r * bhh[192 + 128 + tid]);
            g_last[n*128 + 64 + tid] = (1.f - z)*nn;
        }
    }
}

__global__ __launch_bounds__(128) void k_head(
    const float* __restrict__ pool_W, const float* __restrict__ pool_b,
    const float* __restrict__ mu_W, const float* __restrict__ mu_b,
    const float* __restrict__ logv_W, const float* __restrict__ logv_b,
    const float* __restrict__ dec_W, const float* __restrict__ dec_b,
    const float* __restrict__ lstm_Wih, const float* __restrict__ lstm_bih,
    const float* __restrict__ lstm_bhh,
    float* __restrict__ out)
{
    int b = blockIdx.x, tid = threadIdx.x;
    __shared__ float slast[128], shp[32], smu[32], sdh[64];
    float s = 0.f;
    for (int c = 0; c < 64; c++) s += g_last[(b*64 + c)*128 + tid];
    slast[tid] = s * (1.f/64.f);
    __syncthreads();
    if (tid < 32){
        float acc = pool_b[tid];
        for (int k = 0; k < 128; k++) acc += pool_W[tid*128 + k] * slast[k];
        shp[tid] = fmaxf(acc, 0.f);
    }
    __syncthreads();
    if (tid < 32){
        float acc = mu_b[tid];
        for (int k = 0; k < 32; k++) acc += mu_W[tid*32 + k] * shp[k];
        smu[tid] = acc;
        out[64UL*256*64 + b*32 + tid] = acc;
    } else if (tid < 64){
        int j = tid - 32;
        float acc = logv_b[j];
        for (int k = 0; k < 32; k++) acc += logv_W[j*32 + k] * shp[k];
        out[64UL*256*64 + 2048 + b*32 + j] = acc;
    }
    __syncthreads();
    if (tid < 64){
        float acc = dec_b[tid];
        for (int k = 0; k < 32; k++) acc += dec_W[tid*32 + k] * smu[k];
        sdh[tid] = fmaxf(acc, 0.f);
    }
    __syncthreads();
    for (int gate = tid; gate < 256; gate += 128){
        float acc = lstm_bih[gate] + lstm_bhh[gate];
        for (int k = 0; k < 64; k++) acc += lstm_Wih[gate*64 + k] * sdh[k];
        g_dxg[b*256 + gate] = acc;
    }
}

__global__ __launch_bounds__(256,1) void k_lstm1(const float* __restrict__ Whh)
{
    int b = blockIdx.x, tid = threadIdx.x;
    __shared__ __align__(16) float sh[64];
    __shared__ float sg[256];
    ull w[32];
    const ull* p = (const ull*)(Whh + (size_t)tid*64);
    #pragma unroll
    for (int k = 0; k < 32; k++) w[k] = p[k];
    float dxg = g_dxg[b*256 + tid];
    if (tid < 64) sh[tid] = 0.f;
    float c = 0.f;
    for (int t = 0; t < 256; t++){
        __syncthreads();
        ull a0 = 0, a1 = 0;
        const ulonglong2* v4 = (const ulonglong2*)sh;
        #pragma unroll
        for (int k = 0; k < 16; k++){ ulonglong2 v = v4[k]; fma2(a0, w[2*k], v.x); fma2(a1, w[2*k+1], v.y); }
        sg[tid] = hsum2(a0) + hsum2(a1) + dxg;
        __syncthreads();
        if (tid < 64){
            float i_ = sigf(sg[tid]), f_ = sigf(sg[64+tid]);
            float gg = tanf_(sg[128+tid]), o_ = sigf(sg[192+tid]);
            c = f_*c + i_*gg;
            float h = o_*tanf_(c);
            sh[tid] = h;
            g_h1d[((size_t)b*256 + t)*64 + tid] = h;
        }
    }
}

__global__ __launch_bounds__(256,1) void k_lstm2(
    const float* __restrict__ Wih, const float* __restrict__ Whh,
    const float* __restrict__ bih, const float* __restrict__ bhh,
    const float* __restrict__ out_W, const float* __restrict__ out_b,
    float* __restrict__ out)
{
    int b = blockIdx.x, tid = threadIdx.x;
    __shared__ __align__(16) float sx[64];
    __shared__ __align__(16) float sh[64];
    __shared__ float sg[256];
    __shared__ float soW[64*64];
    for (int i = tid; i < 4096; i += 256){ int c = i >> 6, k = i & 63; soW[k*64 + c] = out_W[i]; }
    ull wi[32], wh[32];
    const ull* p = (const ull*)(Wih + 256UL*64 + (size_t)tid*64);
    const ull* q = (const ull*)(Whh + 256UL*64 + (size_t)tid*64);
    #pragma unroll
    for (int k = 0; k < 32; k++){ wi[k] = p[k]; wh[k] = q[k]; }
    float bias = bih[256 + tid] + bhh[256 + tid];
    if (tid < 64) sh[tid] = 0.f;
    float c = 0.f;
    float ob = (tid >= 64 && tid < 128) ? out_b[tid - 64] : 0.f;
    const float* xb = g_h1d + (size_t)b*256*64;
    for (int t = 0; t < 256; t++){
        if (tid < 64) sx[tid] = xb[t*64 + tid];
        __syncthreads();
        ull a0 = 0, a1 = 0;
        const ulonglong2* x4 = (const ulonglong2*)sx;
        const ulonglong2* h4 = (const ulonglong2*)sh;
        #pragma unroll
        for (int k = 0; k < 16; k++){ ulonglong2 v = x4[k]; fma2(a0, wi[2*k], v.x); fma2(a1, wi[2*k+1], v.y); }
        #pragma unroll
        for (int k = 0; k < 16; k++){ ulonglong2 v = h4[k]; fma2(a0, wh[2*k], v.x); fma2(a1, wh[2*k+1], v.y); }
        sg[tid] = hsum2(a0) + hsum2(a1) + bias;
        __syncthreads();
        if (tid < 64){
            float i_ = sigf(sg[tid]), f_ = sigf(sg[64+tid]);
            float gg = tanf_(sg[128+tid]), o_ = sigf(sg[192+tid]);
            c = f_*c + i_*gg;
            sh[tid] = o_*tanf_(c);
        }
        __syncthreads();
        if (tid >= 64 && tid < 128){
            int cc = tid - 64;
            float acc = ob;
            #pragma unroll 8
            for (int k = 0; k < 64; k++) acc += soW[k*64 + cc] * sh[k];
            out[((size_t)b*256 + t)*64 + cc] = acc;
        }
    }
}

extern "C" void kernel_launch(void* const* d_in, const int* in_sizes, int n_in,
                              void* d_out, int out_size)
{
    const float* x      = (const float*)d_in[0];
    const float* adj1   = (const float*)d_in[1];
    const float* W1     = (const float*)d_in[2];
    const float* b1     = (const float*)d_in[3];
    const float* adj2   = (const float*)d_in[4];
    const float* W2     = (const float*)d_in[5];
    const float* b2     = (const float*)d_in[6];
    const float* ln_g   = (const float*)d_in[7];
    const float* ln_b   = (const float*)d_in[8];
    const float* g0Wih  = (const float*)d_in[9];
    const float* g0Whh  = (const float*)d_in[10];
    const float* g0bih  = (const float*)d_in[11];
    const float* g0bhh  = (const float*)d_in[12];
    const float* g1Wih  = (const float*)d_in[13];
    const float* g1Whh  = (const float*)d_in[14];
    const float* g1bih  = (const float*)d_in[15];
    const float* g1bhh  = (const float*)d_in[16];
    const float* pool_W = (const float*)d_in[17];
    const float* pool_b = (const float*)d_in[18];
    const float* mu_W   = (const float*)d_in[19];
    const float* mu_b   = (const float*)d_in[20];
    const float* logv_W = (const float*)d_in[21];
    const float* logv_b = (const float*)d_in[22];
    const float* dec_W  = (const float*)d_in[23];
    const float* dec_b  = (const float*)d_in[24];
    const float* lWih   = (const float*)d_in[25];
    const float* lWhh   = (const float*)d_in[26];
    const float* lbih   = (const float*)d_in[27];
    const float* lbhh   = (const float*)d_in[28];
    const float* out_W  = (const float*)d_in[29];
    const float* out_b  = (const float*)d_in[30];
    float* out = (float*)d_out;

    k_softmax<<<1, 64>>>(adj1, adj2);
    k_prepW<<<1, 256>>>(g1Wih, g0Wih);
    k_gnn<<<16384, 256>>>(x, W1, b1, W2, b2, ln_g, ln_b);
    k_xproj0<<<1024, 256>>>();
    k_gru0h<<<dim3(512, 2), 192>>>(g0Whh, g0bih, g0bhh);
    k_xproj1<<<1024, 256>>>();
    k_gru1h<<<512, 192>>>(g1Whh, g1bih, g1bhh);
    k_gru1b<<<64, 192>>>(g1Wih, g1Whh, g1bih, g1bhh);
    k_head<<<64, 128>>>(pool_W, pool_b, mu_W, mu_b, logv_W, logv_b,
                        dec_W, dec_b, lWih, lbih, lbhh, out);
    k_lstm1<<<64, 256>>>(lWhh);
    k_lstm2<<<64, 256>>>(lWih, lWhh, lbih, lbhh, out_W, out_b, out);
}